// round 3
// baseline (speedup 1.0000x reference)
#include <cuda_runtime.h>
#include <math.h>

#define B_TOTAL 65536
#define NL 7

// ---- scratch (static device globals: allocation-free rule) ----
__device__ __align__(16) float g_traces[(size_t)B_TOTAL * 224];   // 58.7 MB
__device__ float g_gates[(size_t)B_TOTAL * NL];                   // 1.8 MB

__constant__ int FSRC[21] = {0,1,2, 0,3,4, 0,5,6, 1,3,5, 1,4,6, 2,3,6, 2,4,5};
__constant__ int FPAR[21] = {1,2,0, 3,4,0, 5,6,0, 3,5,1, 4,6,1, 3,6,2, 4,5,2};

__device__ __forceinline__ float warp_sum(float v) {
#pragma unroll
    for (int o = 16; o > 0; o >>= 1) v += __shfl_xor_sync(0xffffffffu, v, o);
    return v;
}

__device__ __forceinline__ float fast_sigmoid(float x) {
    return __fdividef(1.0f, 1.0f + __expf(-x));
}

__device__ __forceinline__ float colony_act(int c, float x) {
    switch (c) {
        case 0: return fmaxf(x, 0.0f);
        case 1: { float e = __expf(2.0f * x); return 1.0f - __fdividef(2.0f, e + 1.0f); }
        case 2: return 0.5f * x * (1.0f + erff(x * 0.7071067811865476f));
        case 3: return x * fast_sigmoid(x);
        case 4: return fmaxf(x, 0.0f) + log1pf(__expf(-fabsf(x)));
        case 5: return fast_sigmoid(x);
        default: return fminf(fmaxf(x, -1.0f), 1.0f);
    }
}

// ============================================================================
// Kernel 1: trace generator + confidence + gates + comp_conf   (4 batches/warp)
// ============================================================================
#define K1_WSZ 27344
#define K1_SCR 1616
#define K1_WARPS 12
#define K1_THREADS (K1_WARPS * 32)
#define K1_SMEM ((K1_WSZ + K1_WARPS * K1_SCR) * 4)

__global__ void __launch_bounds__(K1_THREADS, 1)
colony_k1(const float* __restrict__ z,
          const float* __restrict__ gen_W1, const float* __restrict__ gen_b1,
          const float* __restrict__ gen_g,  const float* __restrict__ gen_be,
          const float* __restrict__ gen_W2, const float* __restrict__ gen_b2,
          const float* __restrict__ cf_W1,  const float* __restrict__ cf_b1,
          const float* __restrict__ cf_W2,  const float* __restrict__ cf_b2,
          const float* __restrict__ gw,     const float* __restrict__ gb,
          float* __restrict__ out_conf)
{
    extern __shared__ float sm[];
    float* sW1  = sm;            // 6272
    float* sb1  = sW1  + 6272;   // 448
    float* sg   = sb1  + 448;    // 448
    float* sbe  = sg   + 448;    // 448
    float* sW2  = sbe  + 448;    // 14336
    float* sb2  = sW2  + 14336;  // 224
    float* scW1 = sb2  + 224;    // 3136
    float* scb1 = scW1 + 3136;   // 224
    float* scW2 = scb1 + 224;    // 224
    float* scb2 = scW2 + 224;    // 8
    float* sgW  = scb2 + 8;      // 1568
    float* sgb  = sgW  + 1568;   // 8
    float* sscr = sgb  + 8;

    const int tid = threadIdx.x;
    for (int i = tid; i < 6272;  i += blockDim.x) sW1[i]  = gen_W1[i];
    for (int i = tid; i < 448;   i += blockDim.x) sb1[i]  = gen_b1[i];
    for (int i = tid; i < 448;   i += blockDim.x) sg[i]   = gen_g[i];
    for (int i = tid; i < 448;   i += blockDim.x) sbe[i]  = gen_be[i];
    for (int i = tid; i < 14336; i += blockDim.x) sW2[i]  = gen_W2[i];
    for (int i = tid; i < 224;   i += blockDim.x) sb2[i]  = gen_b2[i];
    for (int i = tid; i < 3136;  i += blockDim.x) scW1[i] = cf_W1[i];
    for (int i = tid; i < 224;   i += blockDim.x) scb1[i] = cf_b1[i];
    for (int i = tid; i < 224;   i += blockDim.x) scW2[i] = cf_W2[i];
    for (int i = tid; i < 7;     i += blockDim.x) scb2[i] = cf_b2[i];
    for (int i = tid; i < 1568;  i += blockDim.x) sgW[i]  = gw[i];
    for (int i = tid; i < 7;     i += blockDim.x) sgb[i]  = gb[i];
    __syncthreads();

    const int wid  = tid >> 5;
    const int lane = tid & 31;
    float* wscr = sscr + wid * K1_SCR;
    float* wz   = wscr;          // 4*100
    float* wa   = wz + 400;      // 4*64
    float* wtr  = wa + 256;      // 4*224
    float* wcf  = wtr + 896;     // 4*8
    float* wgt  = wcf + 32;      // 4*8

    const int gwarp = blockIdx.x * K1_WARPS + wid;
    const int nwarp = gridDim.x * K1_WARPS;

    for (int b0 = gwarp * 4; b0 < B_TOTAL; b0 += nwarp * 4) {
        int b[4];
#pragma unroll
        for (int u = 0; u < 4; u++) b[u] = min(b0 + u, B_TOTAL - 1);

#pragma unroll
        for (int u = 0; u < 4; u++) {
            const float2* zb = (const float2*)(z + (size_t)b[u] * 98);
            for (int i = lane; i < 49; i += 32) ((float2*)(wz + u * 100))[i] = zb[i];
        }
        __syncwarp();

#pragma unroll
        for (int c = 0; c < NL; c++) {
            // ---- h = z @ W1 + b1 : lane owns cols (2*lane, 2*lane+1) ----
            float2 bias = *(const float2*)&sb1[c * 64 + 2 * lane];
            float2 h[4];
#pragma unroll
            for (int u = 0; u < 4; u++) h[u] = bias;
            const float* w1c = sW1 + c * (14 * 64);
#pragma unroll
            for (int q = 0; q < 14; q++) {
                float2 w = *(const float2*)&w1c[q * 64 + 2 * lane];
#pragma unroll
                for (int u = 0; u < 4; u++) {
                    float v = wz[u * 100 + c * 14 + q];
                    h[u].x = fmaf(v, w.x, h[u].x);
                    h[u].y = fmaf(v, w.y, h[u].y);
                }
            }
            // ---- LayerNorm (one-pass: E[x^2]-m^2) + colony activation ----
            float2 gg = *(const float2*)&sg[c * 64 + 2 * lane];
            float2 bb = *(const float2*)&sbe[c * 64 + 2 * lane];
            float m[4], iv[4];
#pragma unroll
            for (int u = 0; u < 4; u++) {
                float s1 = warp_sum(h[u].x + h[u].y);
                float s2 = warp_sum(h[u].x * h[u].x + h[u].y * h[u].y);
                m[u] = s1 * (1.0f / 64.0f);
                float var = fmaxf(s2 * (1.0f / 64.0f) - m[u] * m[u], 0.0f);
                iv[u] = rsqrtf(var + 1e-5f);
            }
#pragma unroll
            for (int u = 0; u < 4; u++) {
                float ax = colony_act(c, (h[u].x - m[u]) * iv[u] * gg.x + bb.x);
                float ay = colony_act(c, (h[u].y - m[u]) * iv[u] * gg.y + bb.y);
                *(float2*)&wa[u * 64 + 2 * lane] = make_float2(ax, ay);
            }
            __syncwarp();
            // ---- traces = a @ W2 + b2 : lane owns col lane ----
            float t[4];
            float bv = sb2[c * 32 + lane];
#pragma unroll
            for (int u = 0; u < 4; u++) t[u] = bv;
            const float* w2c = sW2 + c * (64 * 32);
#pragma unroll
            for (int i0 = 0; i0 < 64; i0 += 4) {
                float4 v[4];
#pragma unroll
                for (int u = 0; u < 4; u++) v[u] = *(const float4*)&wa[u * 64 + i0];
#pragma unroll
                for (int q = 0; q < 4; q++) {
                    float w = w2c[(i0 + q) * 32 + lane];
#pragma unroll
                    for (int u = 0; u < 4; u++)
                        t[u] = fmaf(((const float*)&v[u])[q], w, t[u]);
                }
            }
#pragma unroll
            for (int u = 0; u < 4; u++) {
                float n = sqrtf(warp_sum(t[u] * t[u]));
                t[u] = __fdividef(t[u], fmaxf(n, 1e-12f));
                wtr[u * 224 + c * 32 + lane] = t[u];
                g_traces[(size_t)b[u] * 224 + c * 32 + lane] = t[u];
            }
            // ---- confidence head ----
            float hc[4];
            float cb = scb1[c * 32 + lane];
#pragma unroll
            for (int u = 0; u < 4; u++) hc[u] = cb;
            const float* cw1 = scW1 + c * (14 * 32);
#pragma unroll
            for (int q = 0; q < 14; q++) {
                float w = cw1[q * 32 + lane];
#pragma unroll
                for (int u = 0; u < 4; u++)
                    hc[u] = fmaf(wz[u * 100 + c * 14 + q], w, hc[u]);
            }
            float w2v = scW2[c * 32 + lane];
#pragma unroll
            for (int u = 0; u < 4; u++) {
                float s = warp_sum(fmaxf(hc[u], 0.0f) * w2v);
                if (lane == 0) wcf[u * 8 + c] = fast_sigmoid(s + scb2[c]);
            }
            __syncwarp();
        }

        // ---- gates ----
#pragma unroll
        for (int l = 0; l < NL; l++) {
            float p[4] = {0.f, 0.f, 0.f, 0.f};
#pragma unroll
            for (int k = 0; k < 7; k++) {
                int i = lane + 32 * k;
                float w = sgW[i * 7 + l];
#pragma unroll
                for (int u = 0; u < 4; u++) p[u] = fmaf(wtr[u * 224 + i], w, p[u]);
            }
#pragma unroll
            for (int u = 0; u < 4; u++) {
                float s = warp_sum(p[u]);
                if (lane == 0) wgt[u * 8 + l] = fast_sigmoid(s + sgb[l]);
            }
        }
        __syncwarp();
#pragma unroll
        for (int u = 0; u < 4; u++) {
            if (lane < 7) g_gates[(size_t)b[u] * 7 + lane] = wgt[u * 8 + lane];
            if (lane < 21) {
                int l = lane / 3;
                float gl = wgt[u * 8 + l];
                float v = (gl >= 0.3f) ? wcf[u * 8 + FSRC[lane]] * wcf[u * 8 + FPAR[lane]] * gl : 0.0f;
                out_conf[(size_t)b[u] * 21 + lane] = v;
            }
        }
        __syncwarp();
    }
}

// ============================================================================
// Kernel 2: line composers  (4 batches/warp)
// ============================================================================
#define K2_WSZ 44576
#define K2_SCR 1184
#define K2_WARPS 10
#define K2_THREADS (K2_WARPS * 32)
#define K2_SMEM ((K2_WSZ + K2_WARPS * K2_SCR) * 4)

__global__ void __launch_bounds__(K2_THREADS, 1)
colony_k2(const float* __restrict__ cW1, const float* __restrict__ cb1,
          const float* __restrict__ cg,  const float* __restrict__ cbe,
          const float* __restrict__ cW2, const float* __restrict__ cb2,
          float* __restrict__ out)
{
    extern __shared__ float sm[];
    float* sW1 = sm;            // 28672
    float* sb1 = sW1 + 28672;   // 448
    float* sg  = sb1 + 448;     // 448
    float* sbe = sg  + 448;     // 448
    float* sW2 = sbe + 448;     // 14336
    float* sb2 = sW2 + 14336;   // 224
    float* sscr = sb2 + 224;

    const int tid = threadIdx.x;
    for (int i = tid; i < 28672; i += blockDim.x) sW1[i] = cW1[i];
    for (int i = tid; i < 448;   i += blockDim.x) sb1[i] = cb1[i];
    for (int i = tid; i < 448;   i += blockDim.x) sg[i]  = cg[i];
    for (int i = tid; i < 448;   i += blockDim.x) sbe[i] = cbe[i];
    for (int i = tid; i < 14336; i += blockDim.x) sW2[i] = cW2[i];
    for (int i = tid; i < 224;   i += blockDim.x) sb2[i] = cb2[i];
    __syncthreads();

    const int wid  = tid >> 5;
    const int lane = tid & 31;
    float* wscr = sscr + wid * K2_SCR;
    float* wtr = wscr;           // 4*224
    float* wch = wtr + 896;      // 4*64
    float* wg  = wch + 256;      // 4*8

    const int gwarp = blockIdx.x * K2_WARPS + wid;
    const int nwarp = gridDim.x * K2_WARPS;

    for (int b0 = gwarp * 4; b0 < B_TOTAL; b0 += nwarp * 4) {
        int b[4];
#pragma unroll
        for (int u = 0; u < 4; u++) b[u] = min(b0 + u, B_TOTAL - 1);

#pragma unroll
        for (int u = 0; u < 4; u++) {
            const float4* gb4 = (const float4*)(g_traces + (size_t)b[u] * 224);
            for (int i = lane; i < 56; i += 32) ((float4*)(wtr + u * 224))[i] = gb4[i];
            if (lane < 7) wg[u * 8 + lane] = g_gates[(size_t)b[u] * 7 + lane];
        }
        __syncwarp();

#pragma unroll
        for (int l = 0; l < NL; l++) {
            float sc4[4];
#pragma unroll
            for (int u = 0; u < 4; u++) {
                float gl = wg[u * 8 + l];
                sc4[u] = (gl >= 0.3f) ? gl : 0.0f;
            }
            const float* W1l = sW1 + l * (64 * 64);
            const float* W2l = sW2 + l * (64 * 32);
            float2 bias1 = *(const float2*)&sb1[l * 64 + 2 * lane];
            float2 gg = *(const float2*)&sg[l * 64 + 2 * lane];
            float2 bb = *(const float2*)&sbe[l * 64 + 2 * lane];
            float b2v = sb2[l * 32 + lane];
#pragma unroll
            for (int p = 0; p < 3; p++) {
                const int scol = FSRC[l * 3 + p] * 32;
                const int pcol = FPAR[l * 3 + p] * 32;
                // ---- stage 1: h = [src,par] @ W1 + b1 ----
                float2 h[4];
#pragma unroll
                for (int u = 0; u < 4; u++) h[u] = bias1;
#pragma unroll
                for (int half = 0; half < 2; half++) {
                    const int icol = half ? pcol : scol;
                    const float* Wh = W1l + half * (32 * 64);
#pragma unroll
                    for (int i0 = 0; i0 < 32; i0 += 4) {
                        float4 v[4];
#pragma unroll
                        for (int u = 0; u < 4; u++)
                            v[u] = *(const float4*)&wtr[u * 224 + icol + i0];
#pragma unroll
                        for (int q = 0; q < 4; q++) {
                            float2 w = *(const float2*)&Wh[(i0 + q) * 64 + 2 * lane];
#pragma unroll
                            for (int u = 0; u < 4; u++) {
                                float vv = ((const float*)&v[u])[q];
                                h[u].x = fmaf(vv, w.x, h[u].x);
                                h[u].y = fmaf(vv, w.y, h[u].y);
                            }
                        }
                    }
                }
                // ---- LN (one-pass) + ReLU ----
                float m[4], iv[4];
#pragma unroll
                for (int u = 0; u < 4; u++) {
                    float s1 = warp_sum(h[u].x + h[u].y);
                    float s2 = warp_sum(h[u].x * h[u].x + h[u].y * h[u].y);
                    m[u] = s1 * (1.0f / 64.0f);
                    float var = fmaxf(s2 * (1.0f / 64.0f) - m[u] * m[u], 0.0f);
                    iv[u] = rsqrtf(var + 1e-5f);
                }
#pragma unroll
                for (int u = 0; u < 4; u++) {
                    float ax = fmaxf((h[u].x - m[u]) * iv[u] * gg.x + bb.x, 0.0f);
                    float ay = fmaxf((h[u].y - m[u]) * iv[u] * gg.y + bb.y, 0.0f);
                    *(float2*)&wch[u * 64 + 2 * lane] = make_float2(ax, ay);
                }
                __syncwarp();
                // ---- stage 2: cv = a @ W2 + b2, l2norm, gate ----
                float t[4];
#pragma unroll
                for (int u = 0; u < 4; u++) t[u] = b2v;
#pragma unroll
                for (int i0 = 0; i0 < 64; i0 += 4) {
                    float4 v[4];
#pragma unroll
                    for (int u = 0; u < 4; u++) v[u] = *(const float4*)&wch[u * 64 + i0];
#pragma unroll
                    for (int q = 0; q < 4; q++) {
                        float w = W2l[(i0 + q) * 32 + lane];
#pragma unroll
                        for (int u = 0; u < 4; u++)
                            t[u] = fmaf(((const float*)&v[u])[q], w, t[u]);
                    }
                }
#pragma unroll
                for (int u = 0; u < 4; u++) {
                    float n = sqrtf(warp_sum(t[u] * t[u]));
                    t[u] = sc4[u] * __fdividef(t[u], fmaxf(n, 1e-12f));
                    out[(((size_t)b[u] * 7 + l) * 3 + p) * 32 + lane] = t[u];
                }
                __syncwarp();
            }
        }
    }
}

// ============================================================================
extern "C" void kernel_launch(void* const* d_in, const int* in_sizes, int n_in,
                              void* d_out, int out_size)
{
    const float* z      = (const float*)d_in[0];
    const float* gen_W1 = (const float*)d_in[1];
    const float* gen_b1 = (const float*)d_in[2];
    const float* gen_g  = (const float*)d_in[3];
    const float* gen_be = (const float*)d_in[4];
    const float* gen_W2 = (const float*)d_in[5];
    const float* gen_b2 = (const float*)d_in[6];
    const float* cf_W1  = (const float*)d_in[7];
    const float* cf_b1  = (const float*)d_in[8];
    const float* cf_W2  = (const float*)d_in[9];
    const float* cf_b2  = (const float*)d_in[10];
    const float* g_W    = (const float*)d_in[11];
    const float* g_b    = (const float*)d_in[12];
    const float* c_W1   = (const float*)d_in[13];
    const float* c_b1   = (const float*)d_in[14];
    const float* c_g    = (const float*)d_in[15];
    const float* c_be   = (const float*)d_in[16];
    const float* c_W2   = (const float*)d_in[17];
    const float* c_b2   = (const float*)d_in[18];

    float* out      = (float*)d_out;                       // composed [B,7,3,32]
    float* out_conf = out + (size_t)B_TOTAL * 672;         // comp_conf [B,7,3]

    cudaFuncSetAttribute(colony_k1, cudaFuncAttributeMaxDynamicSharedMemorySize, K1_SMEM);
    cudaFuncSetAttribute(colony_k2, cudaFuncAttributeMaxDynamicSharedMemorySize, K2_SMEM);

    colony_k1<<<148, K1_THREADS, K1_SMEM>>>(z, gen_W1, gen_b1, gen_g, gen_be, gen_W2, gen_b2,
                                            cf_W1, cf_b1, cf_W2, cf_b2, g_W, g_b, out_conf);
    colony_k2<<<148, K2_THREADS, K2_SMEM>>>(c_W1, c_b1, c_g, c_be, c_W2, c_b2, out);
}

// round 5
// speedup vs baseline: 1.6663x; 1.6663x over previous
#include <cuda_runtime.h>
#include <math.h>

#define B_TOTAL 65536
#define NL 7

typedef unsigned long long u64;

// ---- scratch (static device globals: allocation-free rule) ----
__device__ __align__(16) float g_traces[(size_t)B_TOTAL * 224];   // 58.7 MB
__device__ float g_gates[(size_t)B_TOTAL * NL];                   // 1.8 MB

// FSRC[l*3+j] = FANO[l][j] (colony triple per line); PAR index = (j+1)%3 locally
__constant__ int FSRC[21] = {0,1,2, 0,3,4, 0,5,6, 1,3,5, 1,4,6, 2,3,6, 2,4,5};
__constant__ int FPAR[21] = {1,2,0, 3,4,0, 5,6,0, 3,5,1, 4,6,1, 3,6,2, 4,5,2};

__device__ __forceinline__ float warp_sum(float v) {
#pragma unroll
    for (int o = 16; o > 0; o >>= 1) v += __shfl_xor_sync(0xffffffffu, v, o);
    return v;
}

// packed f32x2 helpers
__device__ __forceinline__ u64 pack2(float x, float y) {
    u64 r; asm("mov.b64 %0, {%1,%2};" : "=l"(r) : "f"(x), "f"(y)); return r;
}
__device__ __forceinline__ float2 unpack2(u64 v) {
    float2 r; asm("mov.b64 {%0,%1}, %2;" : "=f"(r.x), "=f"(r.y) : "l"(v)); return r;
}
__device__ __forceinline__ u64 dup2(float x) { return pack2(x, x); }
__device__ __forceinline__ u64 ffma2(u64 a, u64 b, u64 c) {
    u64 d; asm("fma.rn.f32x2 %0, %1, %2, %3;" : "=l"(d) : "l"(a), "l"(b), "l"(c)); return d;
}

__device__ __forceinline__ float fast_sigmoid(float x) {
    return __fdividef(1.0f, 1.0f + __expf(-x));
}

__device__ __forceinline__ float colony_act(int c, float x) {
    switch (c) {
        case 0: return fmaxf(x, 0.0f);
        case 1: { float e = __expf(2.0f * x); return 1.0f - __fdividef(2.0f, e + 1.0f); }
        case 2: return 0.5f * x * (1.0f + erff(x * 0.7071067811865476f));
        case 3: return x * fast_sigmoid(x);
        case 4: return fmaxf(x, 0.0f) + log1pf(__expf(-fabsf(x)));
        case 5: return fast_sigmoid(x);
        default: return fminf(fmaxf(x, -1.0f), 1.0f);
    }
}

// ============================================================================
// Kernel 1: trace generator + confidence + gates + comp_conf  (2 batches/warp)
// ============================================================================
#define K1_WSZ 27344
#define K1_SCR 808
#define K1_WARPS 16
#define K1_THREADS (K1_WARPS * 32)
#define K1_SMEM ((K1_WSZ + K1_WARPS * K1_SCR) * 4)

__global__ void __launch_bounds__(K1_THREADS, 1)
colony_k1(const float* __restrict__ z,
          const float* __restrict__ gen_W1, const float* __restrict__ gen_b1,
          const float* __restrict__ gen_g,  const float* __restrict__ gen_be,
          const float* __restrict__ gen_W2, const float* __restrict__ gen_b2,
          const float* __restrict__ cf_W1,  const float* __restrict__ cf_b1,
          const float* __restrict__ cf_W2,  const float* __restrict__ cf_b2,
          const float* __restrict__ gw,     const float* __restrict__ gb,
          float* __restrict__ out_conf)
{
    extern __shared__ float sm[];
    float* sW1  = sm;            // 6272
    float* sb1  = sW1  + 6272;   // 448
    float* sg   = sb1  + 448;    // 448
    float* sbe  = sg   + 448;    // 448
    float* sW2  = sbe  + 448;    // 14336
    float* sb2  = sW2  + 14336;  // 224
    float* scW1 = sb2  + 224;    // 3136
    float* scb1 = scW1 + 3136;   // 224
    float* scW2 = scb1 + 224;    // 224
    float* scb2 = scW2 + 224;    // 8
    float* sgW  = scb2 + 8;      // 1568
    float* sgb  = sgW  + 1568;   // 8
    float* sscr = sgb  + 8;

    const int tid = threadIdx.x;
    for (int i = tid; i < 6272;  i += blockDim.x) sW1[i]  = gen_W1[i];
    for (int i = tid; i < 448;   i += blockDim.x) sb1[i]  = gen_b1[i];
    for (int i = tid; i < 448;   i += blockDim.x) sg[i]   = gen_g[i];
    for (int i = tid; i < 448;   i += blockDim.x) sbe[i]  = gen_be[i];
    for (int i = tid; i < 14336; i += blockDim.x) sW2[i]  = gen_W2[i];
    for (int i = tid; i < 224;   i += blockDim.x) sb2[i]  = gen_b2[i];
    for (int i = tid; i < 3136;  i += blockDim.x) scW1[i] = cf_W1[i];
    for (int i = tid; i < 224;   i += blockDim.x) scb1[i] = cf_b1[i];
    for (int i = tid; i < 224;   i += blockDim.x) scW2[i] = cf_W2[i];
    for (int i = tid; i < 7;     i += blockDim.x) scb2[i] = cf_b2[i];
    for (int i = tid; i < 1568;  i += blockDim.x) sgW[i]  = gw[i];
    for (int i = tid; i < 7;     i += blockDim.x) sgb[i]  = gb[i];
    __syncthreads();

    const int wid  = tid >> 5;
    const int lane = tid & 31;
    float* wscr  = sscr + wid * K1_SCR;
    float* wzA   = wscr;         // 100 (98 used)
    float* wzB   = wzA + 100;    // 100
    float* waA   = wzB + 100;    // 64
    float* waB   = waA + 64;     // 64
    float* wtrA  = waB + 64;     // 224
    float* wtrB  = wtrA + 224;   // 224
    float* wcfA  = wtrB + 224;   // 8
    float* wcfB  = wcfA + 8;     // 8
    float* wgtA  = wcfB + 8;     // 8
    float* wgtB  = wgtA + 8;     // 8

    const int gwarp = blockIdx.x * K1_WARPS + wid;
    const int nwarp = gridDim.x * K1_WARPS;

    for (int b0 = gwarp * 2; b0 < B_TOTAL; b0 += nwarp * 2) {
        const int bA = b0, bB = b0 + 1;
        const float2* zA = (const float2*)(z + (size_t)bA * 98);
        const float2* zB = (const float2*)(z + (size_t)bB * 98);
        for (int i = lane; i < 49; i += 32) {
            ((float2*)wzA)[i] = zA[i];
            ((float2*)wzB)[i] = zB[i];
        }
        __syncwarp();

#pragma unroll
        for (int c = 0; c < NL; c++) {
            // ---- h = z @ W1 + b1 : lane owns cols (2*lane, 2*lane+1) ----
            float2 bias = *(const float2*)&sb1[c * 64 + 2 * lane];
            float2 hA = bias, hB = bias;
            const float* w1c = sW1 + c * (14 * 64);
            const float* zcA = wzA + c * 14;
            const float* zcB = wzB + c * 14;
#pragma unroll
            for (int q = 0; q < 14; q++) {
                float2 w = *(const float2*)&w1c[q * 64 + 2 * lane];
                float va = zcA[q], vb = zcB[q];
                hA.x = fmaf(va, w.x, hA.x); hA.y = fmaf(va, w.y, hA.y);
                hB.x = fmaf(vb, w.x, hB.x); hB.y = fmaf(vb, w.y, hB.y);
            }
            // ---- one-pass LN over 64 + colony activation ----
            float s1A = warp_sum(hA.x + hA.y);
            float s1B = warp_sum(hB.x + hB.y);
            float s2A = warp_sum(fmaf(hA.x, hA.x, hA.y * hA.y));
            float s2B = warp_sum(fmaf(hB.x, hB.x, hB.y * hB.y));
            float mA = s1A * (1.0f / 64.0f), mB = s1B * (1.0f / 64.0f);
            float ivA = rsqrtf(fmaxf(s2A * (1.0f / 64.0f) - mA * mA, 0.0f) + 1e-5f);
            float ivB = rsqrtf(fmaxf(s2B * (1.0f / 64.0f) - mB * mB, 0.0f) + 1e-5f);
            float2 gg = *(const float2*)&sg[c * 64 + 2 * lane];
            float2 bb = *(const float2*)&sbe[c * 64 + 2 * lane];
            float2 aA, aB;
            aA.x = colony_act(c, (hA.x - mA) * ivA * gg.x + bb.x);
            aA.y = colony_act(c, (hA.y - mA) * ivA * gg.y + bb.y);
            aB.x = colony_act(c, (hB.x - mB) * ivB * gg.x + bb.x);
            aB.y = colony_act(c, (hB.y - mB) * ivB * gg.y + bb.y);
            *(float2*)&waA[2 * lane] = aA;
            *(float2*)&waB[2 * lane] = aB;
            __syncwarp();
            // ---- traces = a @ W2 + b2 : lane owns col lane ----
            float tA = sb2[c * 32 + lane];
            float tB = tA;
            const float* w2c = sW2 + c * (64 * 32);
#pragma unroll
            for (int i0 = 0; i0 < 64; i0 += 4) {
                float4 vA4 = *(const float4*)&waA[i0];
                float4 vB4 = *(const float4*)&waB[i0];
#pragma unroll
                for (int q = 0; q < 4; q++) {
                    float w = w2c[(i0 + q) * 32 + lane];
                    tA = fmaf(((const float*)&vA4)[q], w, tA);
                    tB = fmaf(((const float*)&vB4)[q], w, tB);
                }
            }
            float nA = sqrtf(warp_sum(tA * tA));
            float nB = sqrtf(warp_sum(tB * tB));
            tA = __fdividef(tA, fmaxf(nA, 1e-12f));
            tB = __fdividef(tB, fmaxf(nB, 1e-12f));
            wtrA[c * 32 + lane] = tA;
            wtrB[c * 32 + lane] = tB;
            g_traces[(size_t)bA * 224 + c * 32 + lane] = tA;
            g_traces[(size_t)bB * 224 + c * 32 + lane] = tB;
            // ---- confidence head ----
            float hcA = scb1[c * 32 + lane];
            float hcB = hcA;
            const float* cw1 = scW1 + c * (14 * 32);
#pragma unroll
            for (int q = 0; q < 14; q++) {
                float w = cw1[q * 32 + lane];
                hcA = fmaf(zcA[q], w, hcA);
                hcB = fmaf(zcB[q], w, hcB);
            }
            float w2v = scW2[c * 32 + lane];
            float sA = warp_sum(fmaxf(hcA, 0.0f) * w2v);
            float sB = warp_sum(fmaxf(hcB, 0.0f) * w2v);
            if (lane == 0) {
                wcfA[c] = fast_sigmoid(sA + scb2[c]);
                wcfB[c] = fast_sigmoid(sB + scb2[c]);
            }
            __syncwarp();
        }

        // ---- gates ----
#pragma unroll
        for (int l = 0; l < NL; l++) {
            float pA = 0.0f, pB = 0.0f;
#pragma unroll
            for (int k = 0; k < 7; k++) {
                int i = lane + 32 * k;
                float w = sgW[i * 7 + l];
                pA = fmaf(wtrA[i], w, pA);
                pB = fmaf(wtrB[i], w, pB);
            }
            pA = warp_sum(pA);
            pB = warp_sum(pB);
            if (lane == 0) {
                wgtA[l] = fast_sigmoid(pA + sgb[l]);
                wgtB[l] = fast_sigmoid(pB + sgb[l]);
            }
        }
        __syncwarp();
        if (lane < 7) {
            g_gates[(size_t)bA * 7 + lane] = wgtA[lane];
            g_gates[(size_t)bB * 7 + lane] = wgtB[lane];
        }
        if (lane < 21) {
            int l = lane / 3;
            int s = FSRC[lane], p = FPAR[lane];
            float gA = wgtA[l], gB = wgtB[l];
            out_conf[(size_t)bA * 21 + lane] = (gA >= 0.3f) ? wcfA[s] * wcfA[p] * gA : 0.0f;
            out_conf[(size_t)bB * 21 + lane] = (gB >= 0.3f) ? wcfB[s] * wcfB[p] * gB : 0.0f;
        }
        __syncwarp();
    }
}

// ============================================================================
// Kernel 2: line composers — line-split blocks, 4 batches/warp, f32x2 FMA
//   grid = 7 lines * 21 blocks; block = 384 thr (12 warps)
//   smem: line weights (6368 floats = 25.5KB) + per-warp scratch
// ============================================================================
#define K2_WARPS 12
#define K2_THREADS (K2_WARPS * 32)
#define K2_BLK_PER_LINE 21
#define K2_GRID (NL * K2_BLK_PER_LINE)
// per-warp scratch in u64 units: wtrAB 96 + wtrCD 96 + wchAB 64 + wchCD 64 = 320 u64
// + 4 floats gates (pad to u64x2) -> 322 -> pad 324
#define K2_SCR_U64 324
#define K2_WSZ 6368
#define K2_SMEM (K2_WSZ * 4 + K2_WARPS * K2_SCR_U64 * 8)

__global__ void __launch_bounds__(K2_THREADS, 1)
colony_k2(const float* __restrict__ cW1, const float* __restrict__ cb1,
          const float* __restrict__ cg,  const float* __restrict__ cbe,
          const float* __restrict__ cW2, const float* __restrict__ cb2,
          float* __restrict__ out)
{
    extern __shared__ __align__(16) float sm[];
    float* sW1l = sm;            // 4096
    float* sW2l = sW1l + 4096;   // 2048
    float* sb1l = sW2l + 2048;   // 64
    float* sgl  = sb1l + 64;     // 64
    float* sbel = sgl  + 64;     // 64
    float* sb2l = sbel + 64;     // 32
    u64*   sscr = (u64*)(sb2l + 32);

    const int line = blockIdx.x % NL;
    const int blk_in_line = blockIdx.x / NL;

    const int tid = threadIdx.x;
    // load line-local weights
    {
        const float* w1 = cW1 + line * 4096;
        const float* w2 = cW2 + line * 2048;
        for (int i = tid; i < 4096; i += blockDim.x) sW1l[i] = w1[i];
        for (int i = tid; i < 2048; i += blockDim.x) sW2l[i] = w2[i];
        if (tid < 64) {
            sb1l[tid] = cb1[line * 64 + tid];
            sgl[tid]  = cg[line * 64 + tid];
            sbel[tid] = cbe[line * 64 + tid];
        }
        if (tid < 32) sb2l[tid] = cb2[line * 32 + tid];
    }
    __syncthreads();

    const int wid  = tid >> 5;
    const int lane = tid & 31;
    u64* wscr  = sscr + wid * K2_SCR_U64;
    u64* wtrAB = wscr;            // [3 colonies][32] packed {A,B}
    u64* wtrCD = wtrAB + 96;      // packed {C,D}
    u64* wchAB = wtrCD + 96;      // [64] packed {A,B}
    u64* wchCD = wchAB + 64;      // [64] packed {C,D}
    float* wg  = (float*)(wchCD + 64);  // 4 gates

    // colony triple of this line
    const int col0 = FSRC[line * 3 + 0];
    const int col1 = FSRC[line * 3 + 1];
    const int col2 = FSRC[line * 3 + 2];

    const int lwarp = blk_in_line * K2_WARPS + wid;          // warp index within line
    const int nlw   = K2_BLK_PER_LINE * K2_WARPS;            // warps per line
    const int ngroups = B_TOTAL / 4;                          // 16384

    for (int g = lwarp; g < ngroups; g += nlw) {
        const int b0 = g * 4;
        int b[4];
#pragma unroll
        for (int u = 0; u < 4; u++) b[u] = b0 + u;   // exact (65536 % 4 == 0)

        // stage traces: lane = row index within colony; pack batch pairs
        {
            const int cols[3] = {col0, col1, col2};
#pragma unroll
            for (int cc = 0; cc < 3; cc++) {
                size_t off = (size_t)cols[cc] * 32 + lane;
                float vA = g_traces[(size_t)b[0] * 224 + off];
                float vB = g_traces[(size_t)b[1] * 224 + off];
                float vC = g_traces[(size_t)b[2] * 224 + off];
                float vD = g_traces[(size_t)b[3] * 224 + off];
                wtrAB[cc * 32 + lane] = pack2(vA, vB);
                wtrCD[cc * 32 + lane] = pack2(vC, vD);
            }
            if (lane < 4) wg[lane] = g_gates[(size_t)b[lane] * 7 + line];
        }
        __syncwarp();

        float scl[4];
#pragma unroll
        for (int u = 0; u < 4; u++) {
            float gl = wg[u];
            scl[u] = (gl >= 0.3f) ? gl : 0.0f;
        }

        float2 bias1 = *(const float2*)&sb1l[2 * lane];
        float2 gg = *(const float2*)&sgl[2 * lane];
        float2 bb = *(const float2*)&sbel[2 * lane];
        float b2v = sb2l[lane];

#pragma unroll
        for (int p = 0; p < 3; p++) {
            const int srcc = p;
            const int parc = (p + 1 == 3) ? 0 : p + 1;
            // ---- stage 1: h = [src,par] @ W1 + b1 (f32x2, batch-pair packed) ----
            u64 hAB0 = dup2(bias1.x), hAB1 = dup2(bias1.y);
            u64 hCD0 = hAB0, hCD1 = hAB1;
#pragma unroll
            for (int half = 0; half < 2; half++) {
                const u64* vAB = wtrAB + (half ? parc : srcc) * 32;
                const u64* vCD = wtrCD + (half ? parc : srcc) * 32;
                const float* Wh = sW1l + half * (32 * 64);
#pragma unroll
                for (int i = 0; i < 32; i++) {
                    u64 vab = vAB[i];
                    u64 vcd = vCD[i];
                    float2 w = *(const float2*)&Wh[i * 64 + 2 * lane];
                    u64 w0 = dup2(w.x), w1 = dup2(w.y);
                    hAB0 = ffma2(vab, w0, hAB0);
                    hAB1 = ffma2(vab, w1, hAB1);
                    hCD0 = ffma2(vcd, w0, hCD0);
                    hCD1 = ffma2(vcd, w1, hCD1);
                }
            }
            // ---- one-pass LN + ReLU (per batch) ----
            float2 hA_ = unpack2(hAB0), hA1_ = unpack2(hAB1);   // .x=A, .y=B
            float2 hC_ = unpack2(hCD0), hC1_ = unpack2(hCD1);   // .x=C, .y=D
            float s1A = warp_sum(hA_.x + hA1_.x);
            float s1B = warp_sum(hA_.y + hA1_.y);
            float s1C = warp_sum(hC_.x + hC1_.x);
            float s1D = warp_sum(hC_.y + hC1_.y);
            float s2A = warp_sum(fmaf(hA_.x, hA_.x, hA1_.x * hA1_.x));
            float s2B = warp_sum(fmaf(hA_.y, hA_.y, hA1_.y * hA1_.y));
            float s2C = warp_sum(fmaf(hC_.x, hC_.x, hC1_.x * hC1_.x));
            float s2D = warp_sum(fmaf(hC_.y, hC_.y, hC1_.y * hC1_.y));
            float mA = s1A * (1.0f / 64.0f), mB = s1B * (1.0f / 64.0f);
            float mC = s1C * (1.0f / 64.0f), mD = s1D * (1.0f / 64.0f);
            float ivA = rsqrtf(fmaxf(s2A * (1.0f / 64.0f) - mA * mA, 0.0f) + 1e-5f);
            float ivB = rsqrtf(fmaxf(s2B * (1.0f / 64.0f) - mB * mB, 0.0f) + 1e-5f);
            float ivC = rsqrtf(fmaxf(s2C * (1.0f / 64.0f) - mC * mC, 0.0f) + 1e-5f);
            float ivD = rsqrtf(fmaxf(s2D * (1.0f / 64.0f) - mD * mD, 0.0f) + 1e-5f);
            float aA0 = fmaxf((hA_.x  - mA) * ivA * gg.x + bb.x, 0.0f);
            float aA1 = fmaxf((hA1_.x - mA) * ivA * gg.y + bb.y, 0.0f);
            float aB0 = fmaxf((hA_.y  - mB) * ivB * gg.x + bb.x, 0.0f);
            float aB1 = fmaxf((hA1_.y - mB) * ivB * gg.y + bb.y, 0.0f);
            float aC0 = fmaxf((hC_.x  - mC) * ivC * gg.x + bb.x, 0.0f);
            float aC1 = fmaxf((hC1_.x - mC) * ivC * gg.y + bb.y, 0.0f);
            float aD0 = fmaxf((hC_.y  - mD) * ivD * gg.x + bb.x, 0.0f);
            float aD1 = fmaxf((hC1_.y - mD) * ivD * gg.y + bb.y, 0.0f);
            wchAB[2 * lane]     = pack2(aA0, aB0);
            wchAB[2 * lane + 1] = pack2(aA1, aB1);
            wchCD[2 * lane]     = pack2(aC0, aD0);
            wchCD[2 * lane + 1] = pack2(aC1, aD1);
            __syncwarp();
            // ---- stage 2: t = a @ W2 + b2 (f32x2, batch-pair packed) ----
            u64 tAB = dup2(b2v), tCD = tAB;
#pragma unroll
            for (int i = 0; i < 64; i++) {
                u64 vab = wchAB[i];
                u64 vcd = wchCD[i];
                u64 wd = dup2(sW2l[i * 32 + lane]);
                tAB = ffma2(vab, wd, tAB);
                tCD = ffma2(vcd, wd, tCD);
            }
            float2 t01 = unpack2(tAB);
            float2 t23 = unpack2(tCD);
            float nA = sqrtf(warp_sum(t01.x * t01.x));
            float nB = sqrtf(warp_sum(t01.y * t01.y));
            float nC = sqrtf(warp_sum(t23.x * t23.x));
            float nD = sqrtf(warp_sum(t23.y * t23.y));
            float oA = scl[0] * __fdividef(t01.x, fmaxf(nA, 1e-12f));
            float oB = scl[1] * __fdividef(t01.y, fmaxf(nB, 1e-12f));
            float oC = scl[2] * __fdividef(t23.x, fmaxf(nC, 1e-12f));
            float oD = scl[3] * __fdividef(t23.y, fmaxf(nD, 1e-12f));
            out[(((size_t)b[0] * 7 + line) * 3 + p) * 32 + lane] = oA;
            out[(((size_t)b[1] * 7 + line) * 3 + p) * 32 + lane] = oB;
            out[(((size_t)b[2] * 7 + line) * 3 + p) * 32 + lane] = oC;
            out[(((size_t)b[3] * 7 + line) * 3 + p) * 32 + lane] = oD;
            __syncwarp();
        }
    }
}

// ============================================================================
extern "C" void kernel_launch(void* const* d_in, const int* in_sizes, int n_in,
                              void* d_out, int out_size)
{
    const float* z      = (const float*)d_in[0];
    const float* gen_W1 = (const float*)d_in[1];
    const float* gen_b1 = (const float*)d_in[2];
    const float* gen_g  = (const float*)d_in[3];
    const float* gen_be = (const float*)d_in[4];
    const float* gen_W2 = (const float*)d_in[5];
    const float* gen_b2 = (const float*)d_in[6];
    const float* cf_W1  = (const float*)d_in[7];
    const float* cf_b1  = (const float*)d_in[8];
    const float* cf_W2  = (const float*)d_in[9];
    const float* cf_b2  = (const float*)d_in[10];
    const float* g_W    = (const float*)d_in[11];
    const float* g_b    = (const float*)d_in[12];
    const float* c_W1   = (const float*)d_in[13];
    const float* c_b1   = (const float*)d_in[14];
    const float* c_g    = (const float*)d_in[15];
    const float* c_be   = (const float*)d_in[16];
    const float* c_W2   = (const float*)d_in[17];
    const float* c_b2   = (const float*)d_in[18];

    float* out      = (float*)d_out;                       // composed [B,7,3,32]
    float* out_conf = out + (size_t)B_TOTAL * 672;         // comp_conf [B,7,3]

    cudaFuncSetAttribute(colony_k1, cudaFuncAttributeMaxDynamicSharedMemorySize, K1_SMEM);
    cudaFuncSetAttribute(colony_k2, cudaFuncAttributeMaxDynamicSharedMemorySize, K2_SMEM);

    colony_k1<<<148, K1_THREADS, K1_SMEM>>>(z, gen_W1, gen_b1, gen_g, gen_be, gen_W2, gen_b2,
                                            cf_W1, cf_b1, cf_W2, cf_b2, g_W, g_b, out_conf);
    colony_k2<<<K2_GRID, K2_THREADS, K2_SMEM>>>(c_W1, c_b1, c_g, c_be, c_W2, c_b2, out);
}

// round 6
// speedup vs baseline: 1.7238x; 1.0345x over previous
#include <cuda_runtime.h>
#include <math.h>

#define B_TOTAL 65536
#define NL 7

typedef unsigned long long u64;

// ---- scratch (static device globals: allocation-free rule) ----
__device__ __align__(16) float g_traces[(size_t)B_TOTAL * 224];   // 58.7 MB
__device__ float g_gates[(size_t)B_TOTAL * NL];                   // 1.8 MB

// FSRC[l*3+j] = FANO[l][j] (colony triple per line); PAR index = (j+1)%3 locally
__constant__ int FSRC[21] = {0,1,2, 0,3,4, 0,5,6, 1,3,5, 1,4,6, 2,3,6, 2,4,5};
__constant__ int FPAR[21] = {1,2,0, 3,4,0, 5,6,0, 3,5,1, 4,6,1, 3,6,2, 4,5,2};

__device__ __forceinline__ float warp_sum(float v) {
#pragma unroll
    for (int o = 16; o > 0; o >>= 1) v += __shfl_xor_sync(0xffffffffu, v, o);
    return v;
}

// packed f32x2 helpers
__device__ __forceinline__ u64 pack2(float x, float y) {
    u64 r; asm("mov.b64 %0, {%1,%2};" : "=l"(r) : "f"(x), "f"(y)); return r;
}
__device__ __forceinline__ float2 unpack2(u64 v) {
    float2 r; asm("mov.b64 {%0,%1}, %2;" : "=f"(r.x), "=f"(r.y) : "l"(v)); return r;
}
__device__ __forceinline__ u64 dup2(float x) { return pack2(x, x); }
__device__ __forceinline__ u64 ffma2(u64 a, u64 b, u64 c) {
    u64 d; asm("fma.rn.f32x2 %0, %1, %2, %3;" : "=l"(d) : "l"(a), "l"(b), "l"(c)); return d;
}

__device__ __forceinline__ float fast_sigmoid(float x) {
    return __fdividef(1.0f, 1.0f + __expf(-x));
}

__device__ __forceinline__ float colony_act(int c, float x) {
    switch (c) {
        case 0: return fmaxf(x, 0.0f);
        case 1: { float e = __expf(2.0f * x); return 1.0f - __fdividef(2.0f, e + 1.0f); }
        case 2: return 0.5f * x * (1.0f + erff(x * 0.7071067811865476f));
        case 3: return x * fast_sigmoid(x);
        case 4: return fmaxf(x, 0.0f) + log1pf(__expf(-fabsf(x)));
        case 5: return fast_sigmoid(x);
        default: return fminf(fmaxf(x, -1.0f), 1.0f);
    }
}

// ============================================================================
// Kernel 1: trace generator + confidence + gates + comp_conf  (2 batches/warp)
// (unchanged from round 5 — proven at ~268us)
// ============================================================================
#define K1_WSZ 27344
#define K1_SCR 808
#define K1_WARPS 16
#define K1_THREADS (K1_WARPS * 32)
#define K1_SMEM ((K1_WSZ + K1_WARPS * K1_SCR) * 4)

__global__ void __launch_bounds__(K1_THREADS, 1)
colony_k1(const float* __restrict__ z,
          const float* __restrict__ gen_W1, const float* __restrict__ gen_b1,
          const float* __restrict__ gen_g,  const float* __restrict__ gen_be,
          const float* __restrict__ gen_W2, const float* __restrict__ gen_b2,
          const float* __restrict__ cf_W1,  const float* __restrict__ cf_b1,
          const float* __restrict__ cf_W2,  const float* __restrict__ cf_b2,
          const float* __restrict__ gw,     const float* __restrict__ gb,
          float* __restrict__ out_conf)
{
    extern __shared__ float sm[];
    float* sW1  = sm;            // 6272
    float* sb1  = sW1  + 6272;   // 448
    float* sg   = sb1  + 448;    // 448
    float* sbe  = sg   + 448;    // 448
    float* sW2  = sbe  + 448;    // 14336
    float* sb2  = sW2  + 14336;  // 224
    float* scW1 = sb2  + 224;    // 3136
    float* scb1 = scW1 + 3136;   // 224
    float* scW2 = scb1 + 224;    // 224
    float* scb2 = scW2 + 224;    // 8
    float* sgW  = scb2 + 8;      // 1568
    float* sgb  = sgW  + 1568;   // 8
    float* sscr = sgb  + 8;

    const int tid = threadIdx.x;
    for (int i = tid; i < 6272;  i += blockDim.x) sW1[i]  = gen_W1[i];
    for (int i = tid; i < 448;   i += blockDim.x) sb1[i]  = gen_b1[i];
    for (int i = tid; i < 448;   i += blockDim.x) sg[i]   = gen_g[i];
    for (int i = tid; i < 448;   i += blockDim.x) sbe[i]  = gen_be[i];
    for (int i = tid; i < 14336; i += blockDim.x) sW2[i]  = gen_W2[i];
    for (int i = tid; i < 224;   i += blockDim.x) sb2[i]  = gen_b2[i];
    for (int i = tid; i < 3136;  i += blockDim.x) scW1[i] = cf_W1[i];
    for (int i = tid; i < 224;   i += blockDim.x) scb1[i] = cf_b1[i];
    for (int i = tid; i < 224;   i += blockDim.x) scW2[i] = cf_W2[i];
    for (int i = tid; i < 7;     i += blockDim.x) scb2[i] = cf_b2[i];
    for (int i = tid; i < 1568;  i += blockDim.x) sgW[i]  = gw[i];
    for (int i = tid; i < 7;     i += blockDim.x) sgb[i]  = gb[i];
    __syncthreads();

    const int wid  = tid >> 5;
    const int lane = tid & 31;
    float* wscr  = sscr + wid * K1_SCR;
    float* wzA   = wscr;         // 100 (98 used)
    float* wzB   = wzA + 100;    // 100
    float* waA   = wzB + 100;    // 64
    float* waB   = waA + 64;     // 64
    float* wtrA  = waB + 64;     // 224
    float* wtrB  = wtrA + 224;   // 224
    float* wcfA  = wtrB + 224;   // 8
    float* wcfB  = wcfA + 8;     // 8
    float* wgtA  = wcfB + 8;     // 8
    float* wgtB  = wgtA + 8;     // 8

    const int gwarp = blockIdx.x * K1_WARPS + wid;
    const int nwarp = gridDim.x * K1_WARPS;

    for (int b0 = gwarp * 2; b0 < B_TOTAL; b0 += nwarp * 2) {
        const int bA = b0, bB = b0 + 1;
        const float2* zA = (const float2*)(z + (size_t)bA * 98);
        const float2* zB = (const float2*)(z + (size_t)bB * 98);
        for (int i = lane; i < 49; i += 32) {
            ((float2*)wzA)[i] = zA[i];
            ((float2*)wzB)[i] = zB[i];
        }
        __syncwarp();

#pragma unroll
        for (int c = 0; c < NL; c++) {
            float2 bias = *(const float2*)&sb1[c * 64 + 2 * lane];
            float2 hA = bias, hB = bias;
            const float* w1c = sW1 + c * (14 * 64);
            const float* zcA = wzA + c * 14;
            const float* zcB = wzB + c * 14;
#pragma unroll
            for (int q = 0; q < 14; q++) {
                float2 w = *(const float2*)&w1c[q * 64 + 2 * lane];
                float va = zcA[q], vb = zcB[q];
                hA.x = fmaf(va, w.x, hA.x); hA.y = fmaf(va, w.y, hA.y);
                hB.x = fmaf(vb, w.x, hB.x); hB.y = fmaf(vb, w.y, hB.y);
            }
            float s1A = warp_sum(hA.x + hA.y);
            float s1B = warp_sum(hB.x + hB.y);
            float s2A = warp_sum(fmaf(hA.x, hA.x, hA.y * hA.y));
            float s2B = warp_sum(fmaf(hB.x, hB.x, hB.y * hB.y));
            float mA = s1A * (1.0f / 64.0f), mB = s1B * (1.0f / 64.0f);
            float ivA = rsqrtf(fmaxf(s2A * (1.0f / 64.0f) - mA * mA, 0.0f) + 1e-5f);
            float ivB = rsqrtf(fmaxf(s2B * (1.0f / 64.0f) - mB * mB, 0.0f) + 1e-5f);
            float2 gg = *(const float2*)&sg[c * 64 + 2 * lane];
            float2 bb = *(const float2*)&sbe[c * 64 + 2 * lane];
            float2 aA, aB;
            aA.x = colony_act(c, (hA.x - mA) * ivA * gg.x + bb.x);
            aA.y = colony_act(c, (hA.y - mA) * ivA * gg.y + bb.y);
            aB.x = colony_act(c, (hB.x - mB) * ivB * gg.x + bb.x);
            aB.y = colony_act(c, (hB.y - mB) * ivB * gg.y + bb.y);
            *(float2*)&waA[2 * lane] = aA;
            *(float2*)&waB[2 * lane] = aB;
            __syncwarp();
            float tA = sb2[c * 32 + lane];
            float tB = tA;
            const float* w2c = sW2 + c * (64 * 32);
#pragma unroll
            for (int i0 = 0; i0 < 64; i0 += 4) {
                float4 vA4 = *(const float4*)&waA[i0];
                float4 vB4 = *(const float4*)&waB[i0];
#pragma unroll
                for (int q = 0; q < 4; q++) {
                    float w = w2c[(i0 + q) * 32 + lane];
                    tA = fmaf(((const float*)&vA4)[q], w, tA);
                    tB = fmaf(((const float*)&vB4)[q], w, tB);
                }
            }
            float nA = rsqrtf(fmaxf(warp_sum(tA * tA), 1e-24f));
            float nB = rsqrtf(fmaxf(warp_sum(tB * tB), 1e-24f));
            tA = tA * nA;
            tB = tB * nB;
            wtrA[c * 32 + lane] = tA;
            wtrB[c * 32 + lane] = tB;
            g_traces[(size_t)bA * 224 + c * 32 + lane] = tA;
            g_traces[(size_t)bB * 224 + c * 32 + lane] = tB;
            float hcA = scb1[c * 32 + lane];
            float hcB = hcA;
            const float* cw1 = scW1 + c * (14 * 32);
#pragma unroll
            for (int q = 0; q < 14; q++) {
                float w = cw1[q * 32 + lane];
                hcA = fmaf(zcA[q], w, hcA);
                hcB = fmaf(zcB[q], w, hcB);
            }
            float w2v = scW2[c * 32 + lane];
            float sA = warp_sum(fmaxf(hcA, 0.0f) * w2v);
            float sB = warp_sum(fmaxf(hcB, 0.0f) * w2v);
            if (lane == 0) {
                wcfA[c] = fast_sigmoid(sA + scb2[c]);
                wcfB[c] = fast_sigmoid(sB + scb2[c]);
            }
            __syncwarp();
        }

#pragma unroll
        for (int l = 0; l < NL; l++) {
            float pA = 0.0f, pB = 0.0f;
#pragma unroll
            for (int k = 0; k < 7; k++) {
                int i = lane + 32 * k;
                float w = sgW[i * 7 + l];
                pA = fmaf(wtrA[i], w, pA);
                pB = fmaf(wtrB[i], w, pB);
            }
            pA = warp_sum(pA);
            pB = warp_sum(pB);
            if (lane == 0) {
                wgtA[l] = fast_sigmoid(pA + sgb[l]);
                wgtB[l] = fast_sigmoid(pB + sgb[l]);
            }
        }
        __syncwarp();
        if (lane < 7) {
            g_gates[(size_t)bA * 7 + lane] = wgtA[lane];
            g_gates[(size_t)bB * 7 + lane] = wgtB[lane];
        }
        if (lane < 21) {
            int l = lane / 3;
            int s = FSRC[lane], p = FPAR[lane];
            float gA = wgtA[l], gB = wgtB[l];
            out_conf[(size_t)bA * 21 + lane] = (gA >= 0.3f) ? wcfA[s] * wcfA[p] * gA : 0.0f;
            out_conf[(size_t)bB * 21 + lane] = (gB >= 0.3f) ? wcfB[s] * wcfB[p] * gB : 0.0f;
        }
        __syncwarp();
    }
}

// ============================================================================
// Kernel 2: line composers — line-split, 4 batches/warp, col-packed f32x2,
//           transposed W2, 2 blocks/SM (256 thr, launch_bounds(256,2))
// ============================================================================
#define K2_WARPS 8
#define K2_THREADS (K2_WARPS * 32)
#define K2_BLK_PER_LINE 42
#define K2_GRID (NL * K2_BLK_PER_LINE)
// smem floats: W1 (u64 layout) 4096 | W2t 32*68=2176 | b1 64 | g 64 | be 64 | b2 32 = 6496
// per-warp scratch (u64 units): wtr4 96 float4 = 192 u64 | wchAB 64 | wchCD 64 | wg pad 4 = 324
#define K2_WSZ 6496
#define K2_SCR_U64 324
#define K2_SMEM (K2_WSZ * 4 + K2_WARPS * K2_SCR_U64 * 8)

__global__ void __launch_bounds__(K2_THREADS, 2)
colony_k2(const float* __restrict__ cW1, const float* __restrict__ cb1,
          const float* __restrict__ cg,  const float* __restrict__ cbe,
          const float* __restrict__ cW2, const float* __restrict__ cb2,
          float* __restrict__ out)
{
    extern __shared__ __align__(16) float sm[];
    float* sW1l = sm;            // 4096 (row-major [64][64]; u64 access per col-pair)
    float* sW2t = sW1l + 4096;   // 2176 = 32 rows (out col) * 68 (padded K)
    float* sb1l = sW2t + 2176;   // 64
    float* sgl  = sb1l + 64;     // 64
    float* sbel = sgl  + 64;     // 64
    float* sb2l = sbel + 64;     // 32
    u64*   sscr = (u64*)(sb2l + 32);

    const int line = blockIdx.x % NL;
    const int tid = threadIdx.x;
    {
        const float* w1 = cW1 + line * 4096;
        const float* w2 = cW2 + line * 2048;
        for (int i = tid; i < 4096; i += blockDim.x) sW1l[i] = w1[i];
        // transpose W2: sW2t[col*68 + row] = W2[row*32 + col]
        for (int i = tid; i < 2048; i += blockDim.x) {
            int row = i >> 5, col = i & 31;
            sW2t[col * 68 + row] = w2[i];
        }
        if (tid < 64) {
            sb1l[tid] = cb1[line * 64 + tid];
            sgl[tid]  = cg[line * 64 + tid];
            sbel[tid] = cbe[line * 64 + tid];
        }
        if (tid < 32) sb2l[tid] = cb2[line * 32 + tid];
    }
    __syncthreads();

    const int wid  = tid >> 5;
    const int lane = tid & 31;
    u64* wscr  = sscr + wid * K2_SCR_U64;
    float4* wtr4 = (float4*)wscr;        // [3 colonies][32] float4 {A,B,C,D}
    u64* wchAB = wscr + 192;             // [64] packed {A,B}
    u64* wchCD = wchAB + 64;             // [64] packed {C,D}
    float* wg  = (float*)(wchCD + 64);   // 4 gates

    const int col0 = FSRC[line * 3 + 0];
    const int col1 = FSRC[line * 3 + 1];
    const int col2 = FSRC[line * 3 + 2];

    const int blk_in_line = blockIdx.x / NL;
    const int lwarp = blk_in_line * K2_WARPS + wid;
    const int nlw   = K2_BLK_PER_LINE * K2_WARPS;
    const int ngroups = B_TOTAL / 4;

    const u64 hbias = *(const u64*)&sb1l[2 * lane];
    const float2 gg = *(const float2*)&sgl[2 * lane];
    const float2 bb = *(const float2*)&sbel[2 * lane];
    const float b2v = sb2l[lane];
    const float4* wrow = (const float4*)&sW2t[lane * 68];   // 272B offset, 16B aligned

    for (int g = lwarp; g < ngroups; g += nlw) {
        const int b0 = g * 4;

        // stage traces interleaved by batch: wtr4[cc*32+lane] = {A,B,C,D}
        {
            const int cols[3] = {col0, col1, col2};
#pragma unroll
            for (int cc = 0; cc < 3; cc++) {
                size_t off = (size_t)cols[cc] * 32 + lane;
                float vA = g_traces[(size_t)(b0 + 0) * 224 + off];
                float vB = g_traces[(size_t)(b0 + 1) * 224 + off];
                float vC = g_traces[(size_t)(b0 + 2) * 224 + off];
                float vD = g_traces[(size_t)(b0 + 3) * 224 + off];
                wtr4[cc * 32 + lane] = make_float4(vA, vB, vC, vD);
            }
            if (lane < 4) wg[lane] = g_gates[(size_t)(b0 + lane) * 7 + line];
        }
        __syncwarp();

        float scl[4];
#pragma unroll
        for (int u = 0; u < 4; u++) {
            float gl = wg[u];
            scl[u] = (gl >= 0.3f) ? gl : 0.0f;
        }

#pragma unroll
        for (int p = 0; p < 3; p++) {
            const int srcc = p;
            const int parc = (p + 1 == 3) ? 0 : p + 1;
            // ---- stage 1: col-packed accumulators, one per batch ----
            u64 h0 = hbias, h1 = hbias, h2 = hbias, h3 = hbias;
#pragma unroll
            for (int half = 0; half < 2; half++) {
                const float4* v4 = wtr4 + (half ? parc : srcc) * 32;
                const u64* Wh = (const u64*)(sW1l + half * 2048);
#pragma unroll
                for (int i = 0; i < 32; i++) {
                    float4 v = v4[i];                 // 16B broadcast
                    u64 w = Wh[i * 32 + lane];        // {W[i][2l], W[i][2l+1]}
                    h0 = ffma2(dup2(v.x), w, h0);
                    h1 = ffma2(dup2(v.y), w, h1);
                    h2 = ffma2(dup2(v.z), w, h2);
                    h3 = ffma2(dup2(v.w), w, h3);
                }
            }
            // ---- one-pass LN + ReLU per batch ----
            float2 f0 = unpack2(h0), f1 = unpack2(h1), f2 = unpack2(h2), f3 = unpack2(h3);
            float s1A = warp_sum(f0.x + f0.y);
            float s1B = warp_sum(f1.x + f1.y);
            float s1C = warp_sum(f2.x + f2.y);
            float s1D = warp_sum(f3.x + f3.y);
            float s2A = warp_sum(fmaf(f0.x, f0.x, f0.y * f0.y));
            float s2B = warp_sum(fmaf(f1.x, f1.x, f1.y * f1.y));
            float s2C = warp_sum(fmaf(f2.x, f2.x, f2.y * f2.y));
            float s2D = warp_sum(fmaf(f3.x, f3.x, f3.y * f3.y));
            float mA = s1A * (1.0f / 64.0f), mB = s1B * (1.0f / 64.0f);
            float mC = s1C * (1.0f / 64.0f), mD = s1D * (1.0f / 64.0f);
            float ivA = rsqrtf(fmaxf(s2A * (1.0f / 64.0f) - mA * mA, 0.0f) + 1e-5f);
            float ivB = rsqrtf(fmaxf(s2B * (1.0f / 64.0f) - mB * mB, 0.0f) + 1e-5f);
            float ivC = rsqrtf(fmaxf(s2C * (1.0f / 64.0f) - mC * mC, 0.0f) + 1e-5f);
            float ivD = rsqrtf(fmaxf(s2D * (1.0f / 64.0f) - mD * mD, 0.0f) + 1e-5f);
            float aA0 = fmaxf((f0.x - mA) * ivA * gg.x + bb.x, 0.0f);
            float aA1 = fmaxf((f0.y - mA) * ivA * gg.y + bb.y, 0.0f);
            float aB0 = fmaxf((f1.x - mB) * ivB * gg.x + bb.x, 0.0f);
            float aB1 = fmaxf((f1.y - mB) * ivB * gg.y + bb.y, 0.0f);
            float aC0 = fmaxf((f2.x - mC) * ivC * gg.x + bb.x, 0.0f);
            float aC1 = fmaxf((f2.y - mC) * ivC * gg.y + bb.y, 0.0f);
            float aD0 = fmaxf((f3.x - mD) * ivD * gg.x + bb.x, 0.0f);
            float aD1 = fmaxf((f3.y - mD) * ivD * gg.y + bb.y, 0.0f);
            wchAB[2 * lane]     = pack2(aA0, aB0);
            wchAB[2 * lane + 1] = pack2(aA1, aB1);
            wchCD[2 * lane]     = pack2(aC0, aD0);
            wchCD[2 * lane + 1] = pack2(aC1, aD1);
            __syncwarp();
            // ---- stage 2: batch-packed, transposed-W2 row per lane ----
            u64 tAB = dup2(b2v), tCD = tAB;
#pragma unroll
            for (int i0 = 0; i0 < 64; i0 += 4) {
                float4 w4 = wrow[i0 >> 2];                          // 4 K-rows of this lane's col
                ulonglong2 ab01 = *(const ulonglong2*)&wchAB[i0];
                ulonglong2 ab23 = *(const ulonglong2*)&wchAB[i0 + 2];
                ulonglong2 cd01 = *(const ulonglong2*)&wchCD[i0];
                ulonglong2 cd23 = *(const ulonglong2*)&wchCD[i0 + 2];
                tAB = ffma2(ab01.x, dup2(w4.x), tAB);
                tCD = ffma2(cd01.x, dup2(w4.x), tCD);
                tAB = ffma2(ab01.y, dup2(w4.y), tAB);
                tCD = ffma2(cd01.y, dup2(w4.y), tCD);
                tAB = ffma2(ab23.x, dup2(w4.z), tAB);
                tCD = ffma2(cd23.x, dup2(w4.z), tCD);
                tAB = ffma2(ab23.y, dup2(w4.w), tAB);
                tCD = ffma2(cd23.y, dup2(w4.w), tCD);
            }
            float2 t01 = unpack2(tAB);
            float2 t23 = unpack2(tCD);
            float nA = rsqrtf(fmaxf(warp_sum(t01.x * t01.x), 1e-24f));
            float nB = rsqrtf(fmaxf(warp_sum(t01.y * t01.y), 1e-24f));
            float nC = rsqrtf(fmaxf(warp_sum(t23.x * t23.x), 1e-24f));
            float nD = rsqrtf(fmaxf(warp_sum(t23.y * t23.y), 1e-24f));
            out[(((size_t)(b0 + 0) * 7 + line) * 3 + p) * 32 + lane] = scl[0] * t01.x * nA;
            out[(((size_t)(b0 + 1) * 7 + line) * 3 + p) * 32 + lane] = scl[1] * t01.y * nB;
            out[(((size_t)(b0 + 2) * 7 + line) * 3 + p) * 32 + lane] = scl[2] * t23.x * nC;
            out[(((size_t)(b0 + 3) * 7 + line) * 3 + p) * 32 + lane] = scl[3] * t23.y * nD;
            __syncwarp();
        }
    }
}

// ============================================================================
extern "C" void kernel_launch(void* const* d_in, const int* in_sizes, int n_in,
                              void* d_out, int out_size)
{
    const float* z      = (const float*)d_in[0];
    const float* gen_W1 = (const float*)d_in[1];
    const float* gen_b1 = (const float*)d_in[2];
    const float* gen_g  = (const float*)d_in[3];
    const float* gen_be = (const float*)d_in[4];
    const float* gen_W2 = (const float*)d_in[5];
    const float* gen_b2 = (const float*)d_in[6];
    const float* cf_W1  = (const float*)d_in[7];
    const float* cf_b1  = (const float*)d_in[8];
    const float* cf_W2  = (const float*)d_in[9];
    const float* cf_b2  = (const float*)d_in[10];
    const float* g_W    = (const float*)d_in[11];
    const float* g_b    = (const float*)d_in[12];
    const float* c_W1   = (const float*)d_in[13];
    const float* c_b1   = (const float*)d_in[14];
    const float* c_g    = (const float*)d_in[15];
    const float* c_be   = (const float*)d_in[16];
    const float* c_W2   = (const float*)d_in[17];
    const float* c_b2   = (const float*)d_in[18];

    float* out      = (float*)d_out;                       // composed [B,7,3,32]
    float* out_conf = out + (size_t)B_TOTAL * 672;         // comp_conf [B,7,3]

    cudaFuncSetAttribute(colony_k1, cudaFuncAttributeMaxDynamicSharedMemorySize, K1_SMEM);
    cudaFuncSetAttribute(colony_k2, cudaFuncAttributeMaxDynamicSharedMemorySize, K2_SMEM);

    colony_k1<<<148, K1_THREADS, K1_SMEM>>>(z, gen_W1, gen_b1, gen_g, gen_be, gen_W2, gen_b2,
                                            cf_W1, cf_b1, cf_W2, cf_b2, g_W, g_b, out_conf);
    colony_k2<<<K2_GRID, K2_THREADS, K2_SMEM>>>(c_W1, c_b1, c_g, c_be, c_W2, c_b2, out);
}

// round 9
// speedup vs baseline: 1.7513x; 1.0160x over previous
#include <cuda_runtime.h>
#include <math.h>

#define B_TOTAL 65536
#define NL 7

typedef unsigned long long u64;

// ---- scratch (static device globals: allocation-free rule) ----
__device__ __align__(16) float g_traces[(size_t)B_TOTAL * 224];   // 58.7 MB
__device__ float g_gates[(size_t)B_TOTAL * NL];                   // 1.8 MB

// FSRC[l*3+j] = FANO[l][j] (colony triple per line); PAR index = (j+1)%3 locally
__constant__ int FSRC[21] = {0,1,2, 0,3,4, 0,5,6, 1,3,5, 1,4,6, 2,3,6, 2,4,5};
__constant__ int FPAR[21] = {1,2,0, 3,4,0, 5,6,0, 3,5,1, 4,6,1, 3,6,2, 4,5,2};

__device__ __forceinline__ float warp_sum(float v) {
#pragma unroll
    for (int o = 16; o > 0; o >>= 1) v += __shfl_xor_sync(0xffffffffu, v, o);
    return v;
}

// packed f32x2 helpers
__device__ __forceinline__ u64 pack2(float x, float y) {
    u64 r; asm("mov.b64 %0, {%1,%2};" : "=l"(r) : "f"(x), "f"(y)); return r;
}
__device__ __forceinline__ float2 unpack2(u64 v) {
    float2 r; asm("mov.b64 {%0,%1}, %2;" : "=f"(r.x), "=f"(r.y) : "l"(v)); return r;
}
__device__ __forceinline__ u64 dup2(float x) { return pack2(x, x); }
__device__ __forceinline__ u64 ffma2(u64 a, u64 b, u64 c) {
    u64 d; asm("fma.rn.f32x2 %0, %1, %2, %3;" : "=l"(d) : "l"(a), "l"(b), "l"(c)); return d;
}
__device__ __forceinline__ u64 add2(u64 a, u64 b) {
    u64 d; asm("add.rn.f32x2 %0, %1, %2;" : "=l"(d) : "l"(a), "l"(b)); return d;
}
__device__ __forceinline__ u64 mul2(u64 a, u64 b) {
    u64 d; asm("mul.rn.f32x2 %0, %1, %2;" : "=l"(d) : "l"(a), "l"(b)); return d;
}

__device__ __forceinline__ float fast_sigmoid(float x) {
    return __fdividef(1.0f, 1.0f + __expf(-x));
}

__device__ __forceinline__ float colony_act(int c, float x) {
    switch (c) {
        case 0: return fmaxf(x, 0.0f);
        case 1: { float e = __expf(2.0f * x); return 1.0f - __fdividef(2.0f, e + 1.0f); }
        case 2: return 0.5f * x * (1.0f + erff(x * 0.7071067811865476f));
        case 3: return x * fast_sigmoid(x);
        case 4: return fmaxf(x, 0.0f) + log1pf(__expf(-fabsf(x)));
        case 5: return fast_sigmoid(x);
        default: return fminf(fmaxf(x, -1.0f), 1.0f);
    }
}

// ============================================================================
// Kernel 1: trace generator + confidence + gates + comp_conf  (2 batches/warp)
// (unchanged from round 6 — proven)
// ============================================================================
#define K1_WSZ 27344
#define K1_SCR 808
#define K1_WARPS 16
#define K1_THREADS (K1_WARPS * 32)
#define K1_SMEM ((K1_WSZ + K1_WARPS * K1_SCR) * 4)

__global__ void __launch_bounds__(K1_THREADS, 1)
colony_k1(const float* __restrict__ z,
          const float* __restrict__ gen_W1, const float* __restrict__ gen_b1,
          const float* __restrict__ gen_g,  const float* __restrict__ gen_be,
          const float* __restrict__ gen_W2, const float* __restrict__ gen_b2,
          const float* __restrict__ cf_W1,  const float* __restrict__ cf_b1,
          const float* __restrict__ cf_W2,  const float* __restrict__ cf_b2,
          const float* __restrict__ gw,     const float* __restrict__ gb,
          float* __restrict__ out_conf)
{
    extern __shared__ float sm[];
    float* sW1  = sm;            // 6272
    float* sb1  = sW1  + 6272;   // 448
    float* sg   = sb1  + 448;    // 448
    float* sbe  = sg   + 448;    // 448
    float* sW2  = sbe  + 448;    // 14336
    float* sb2  = sW2  + 14336;  // 224
    float* scW1 = sb2  + 224;    // 3136
    float* scb1 = scW1 + 3136;   // 224
    float* scW2 = scb1 + 224;    // 224
    float* scb2 = scW2 + 224;    // 8
    float* sgW  = scb2 + 8;      // 1568
    float* sgb  = sgW  + 1568;   // 8
    float* sscr = sgb  + 8;

    const int tid = threadIdx.x;
    for (int i = tid; i < 6272;  i += blockDim.x) sW1[i]  = gen_W1[i];
    for (int i = tid; i < 448;   i += blockDim.x) sb1[i]  = gen_b1[i];
    for (int i = tid; i < 448;   i += blockDim.x) sg[i]   = gen_g[i];
    for (int i = tid; i < 448;   i += blockDim.x) sbe[i]  = gen_be[i];
    for (int i = tid; i < 14336; i += blockDim.x) sW2[i]  = gen_W2[i];
    for (int i = tid; i < 224;   i += blockDim.x) sb2[i]  = gen_b2[i];
    for (int i = tid; i < 3136;  i += blockDim.x) scW1[i] = cf_W1[i];
    for (int i = tid; i < 224;   i += blockDim.x) scb1[i] = cf_b1[i];
    for (int i = tid; i < 224;   i += blockDim.x) scW2[i] = cf_W2[i];
    for (int i = tid; i < 7;     i += blockDim.x) scb2[i] = cf_b2[i];
    for (int i = tid; i < 1568;  i += blockDim.x) sgW[i]  = gw[i];
    for (int i = tid; i < 7;     i += blockDim.x) sgb[i]  = gb[i];
    __syncthreads();

    const int wid  = tid >> 5;
    const int lane = tid & 31;
    float* wscr  = sscr + wid * K1_SCR;
    float* wzA   = wscr;         // 100 (98 used)
    float* wzB   = wzA + 100;    // 100
    float* waA   = wzB + 100;    // 64
    float* waB   = waA + 64;     // 64
    float* wtrA  = waB + 64;     // 224
    float* wtrB  = wtrA + 224;   // 224
    float* wcfA  = wtrB + 224;   // 8
    float* wcfB  = wcfA + 8;     // 8
    float* wgtA  = wcfB + 8;     // 8
    float* wgtB  = wgtA + 8;     // 8

    const int gwarp = blockIdx.x * K1_WARPS + wid;
    const int nwarp = gridDim.x * K1_WARPS;

    for (int b0 = gwarp * 2; b0 < B_TOTAL; b0 += nwarp * 2) {
        const int bA = b0, bB = b0 + 1;
        const float2* zA = (const float2*)(z + (size_t)bA * 98);
        const float2* zB = (const float2*)(z + (size_t)bB * 98);
        for (int i = lane; i < 49; i += 32) {
            ((float2*)wzA)[i] = zA[i];
            ((float2*)wzB)[i] = zB[i];
        }
        __syncwarp();

#pragma unroll
        for (int c = 0; c < NL; c++) {
            float2 bias = *(const float2*)&sb1[c * 64 + 2 * lane];
            float2 hA = bias, hB = bias;
            const float* w1c = sW1 + c * (14 * 64);
            const float* zcA = wzA + c * 14;
            const float* zcB = wzB + c * 14;
#pragma unroll
            for (int q = 0; q < 14; q++) {
                float2 w = *(const float2*)&w1c[q * 64 + 2 * lane];
                float va = zcA[q], vb = zcB[q];
                hA.x = fmaf(va, w.x, hA.x); hA.y = fmaf(va, w.y, hA.y);
                hB.x = fmaf(vb, w.x, hB.x); hB.y = fmaf(vb, w.y, hB.y);
            }
            float s1A = warp_sum(hA.x + hA.y);
            float s1B = warp_sum(hB.x + hB.y);
            float s2A = warp_sum(fmaf(hA.x, hA.x, hA.y * hA.y));
            float s2B = warp_sum(fmaf(hB.x, hB.x, hB.y * hB.y));
            float mA = s1A * (1.0f / 64.0f), mB = s1B * (1.0f / 64.0f);
            float ivA = rsqrtf(fmaxf(s2A * (1.0f / 64.0f) - mA * mA, 0.0f) + 1e-5f);
            float ivB = rsqrtf(fmaxf(s2B * (1.0f / 64.0f) - mB * mB, 0.0f) + 1e-5f);
            float2 gg = *(const float2*)&sg[c * 64 + 2 * lane];
            float2 bb = *(const float2*)&sbe[c * 64 + 2 * lane];
            float2 aA, aB;
            aA.x = colony_act(c, (hA.x - mA) * ivA * gg.x + bb.x);
            aA.y = colony_act(c, (hA.y - mA) * ivA * gg.y + bb.y);
            aB.x = colony_act(c, (hB.x - mB) * ivB * gg.x + bb.x);
            aB.y = colony_act(c, (hB.y - mB) * ivB * gg.y + bb.y);
            *(float2*)&waA[2 * lane] = aA;
            *(float2*)&waB[2 * lane] = aB;
            __syncwarp();
            float tA = sb2[c * 32 + lane];
            float tB = tA;
            const float* w2c = sW2 + c * (64 * 32);
#pragma unroll
            for (int i0 = 0; i0 < 64; i0 += 4) {
                float4 vA4 = *(const float4*)&waA[i0];
                float4 vB4 = *(const float4*)&waB[i0];
#pragma unroll
                for (int q = 0; q < 4; q++) {
                    float w = w2c[(i0 + q) * 32 + lane];
                    tA = fmaf(((const float*)&vA4)[q], w, tA);
                    tB = fmaf(((const float*)&vB4)[q], w, tB);
                }
            }
            float nA = rsqrtf(fmaxf(warp_sum(tA * tA), 1e-24f));
            float nB = rsqrtf(fmaxf(warp_sum(tB * tB), 1e-24f));
            tA = tA * nA;
            tB = tB * nB;
            wtrA[c * 32 + lane] = tA;
            wtrB[c * 32 + lane] = tB;
            g_traces[(size_t)bA * 224 + c * 32 + lane] = tA;
            g_traces[(size_t)bB * 224 + c * 32 + lane] = tB;
            float hcA = scb1[c * 32 + lane];
            float hcB = hcA;
            const float* cw1 = scW1 + c * (14 * 32);
#pragma unroll
            for (int q = 0; q < 14; q++) {
                float w = cw1[q * 32 + lane];
                hcA = fmaf(zcA[q], w, hcA);
                hcB = fmaf(zcB[q], w, hcB);
            }
            float w2v = scW2[c * 32 + lane];
            float sA = warp_sum(fmaxf(hcA, 0.0f) * w2v);
            float sB = warp_sum(fmaxf(hcB, 0.0f) * w2v);
            if (lane == 0) {
                wcfA[c] = fast_sigmoid(sA + scb2[c]);
                wcfB[c] = fast_sigmoid(sB + scb2[c]);
            }
            __syncwarp();
        }

#pragma unroll
        for (int l = 0; l < NL; l++) {
            float pA = 0.0f, pB = 0.0f;
#pragma unroll
            for (int k = 0; k < 7; k++) {
                int i = lane + 32 * k;
                float w = sgW[i * 7 + l];
                pA = fmaf(wtrA[i], w, pA);
                pB = fmaf(wtrB[i], w, pB);
            }
            pA = warp_sum(pA);
            pB = warp_sum(pB);
            if (lane == 0) {
                wgtA[l] = fast_sigmoid(pA + sgb[l]);
                wgtB[l] = fast_sigmoid(pB + sgb[l]);
            }
        }
        __syncwarp();
        if (lane < 7) {
            g_gates[(size_t)bA * 7 + lane] = wgtA[lane];
            g_gates[(size_t)bB * 7 + lane] = wgtB[lane];
        }
        if (lane < 21) {
            int l = lane / 3;
            int s = FSRC[lane], p = FPAR[lane];
            float gA = wgtA[l], gB = wgtB[l];
            out_conf[(size_t)bA * 21 + lane] = (gA >= 0.3f) ? wcfA[s] * wcfA[p] * gA : 0.0f;
            out_conf[(size_t)bB * 21 + lane] = (gB >= 0.3f) ? wcfB[s] * wcfB[p] * gB : 0.0f;
        }
        __syncwarp();
    }
}

// ============================================================================
// Kernel 2: lane = batch; h staged through private smem row (NO big reg arrays
// live across stages → no spill). Weights are broadcast LDS.128. Private rows
// stride 164 floats (≡4 mod 32) → conflict-free float4 access.
// ============================================================================
#define K2_WARPS 8
#define K2_THREADS (K2_WARPS * 32)
#define K2_BLK_PER_LINE 21
#define K2_GRID (NL * K2_BLK_PER_LINE)
#define K2_ROW 164
// smem floats: W1 4096 | W2 2048 | b1 64 | g 64 | be 64 | b2 32 | rows 8*32*164
#define K2_WSZ (6368 + K2_WARPS * 32 * K2_ROW)
#define K2_SMEM (K2_WSZ * 4)

__global__ void __launch_bounds__(K2_THREADS, 1)
colony_k2(const float* __restrict__ cW1, const float* __restrict__ cb1,
          const float* __restrict__ cg,  const float* __restrict__ cbe,
          const float* __restrict__ cW2, const float* __restrict__ cb2,
          float* __restrict__ out)
{
    extern __shared__ __align__(16) float sm[];
    float* sW1 = sm;            // [64][64] row-major
    float* sW2 = sW1 + 4096;    // [64][32] row-major
    float* sb1 = sW2 + 2048;    // 64
    float* sgl = sb1 + 64;      // 64
    float* sbe = sgl + 64;      // 64
    float* sb2 = sbe + 64;      // 32
    float* stile = sb2 + 32;    // [8 warps][32 lanes][164]

    const int line = blockIdx.x % NL;
    const int tid = threadIdx.x;
    {
        const float* w1 = cW1 + line * 4096;
        const float* w2 = cW2 + line * 2048;
        for (int i = tid; i < 4096; i += blockDim.x) sW1[i] = w1[i];
        for (int i = tid; i < 2048; i += blockDim.x) sW2[i] = w2[i];
        if (tid < 64) {
            sb1[tid] = cb1[line * 64 + tid];
            sgl[tid] = cg[line * 64 + tid];
            sbe[tid] = cbe[line * 64 + tid];
        }
        if (tid < 32) sb2[tid] = cb2[line * 32 + tid];
    }
    __syncthreads();

    const int wid  = tid >> 5;
    const int lane = tid & 31;
    float* myrow = stile + (wid * 32 + lane) * K2_ROW;   // inputs [0,96), h [96,160)

    const int col0 = FSRC[line * 3 + 0];
    const int col1 = FSRC[line * 3 + 1];
    const int col2 = FSRC[line * 3 + 2];

    const int lwarp = (blockIdx.x / NL) * K2_WARPS + wid;
    const int nlw   = K2_BLK_PER_LINE * K2_WARPS;   // 168
    const int ngroups = B_TOTAL / 32;               // 2048

    for (int g = lwarp; g < ngroups; g += nlw) {
        const int b = g * 32 + lane;   // this lane's batch

        // stage this lane's 3 colony trace chunks into its private row
        {
            const int cols[3] = {col0, col1, col2};
#pragma unroll
            for (int cc = 0; cc < 3; cc++) {
                const float4* src = (const float4*)(g_traces + (size_t)b * 224 + cols[cc] * 32);
                float4* dst = (float4*)(myrow + cc * 32);
#pragma unroll
                for (int k = 0; k < 8; k++) dst[k] = src[k];
            }
        }
        const float gate = g_gates[(size_t)b * 7 + line];
        const float scl = (gate >= 0.3f) ? gate : 0.0f;

#pragma unroll
        for (int p = 0; p < 3; p++) {
            const float* xA = myrow + p * 32;
            const float* xB = myrow + ((p + 1 == 3) ? 0 : p + 1) * 32;

            // ---- stage 1: h = [xA,xB] @ W1 + b1, in two 32-col chunks ----
            float s1 = 0.0f, s2 = 0.0f;
#pragma unroll
            for (int chunk = 0; chunk < 2; chunk++) {
                u64 hreg[16];
                {
                    const ulonglong2* bp = (const ulonglong2*)(sb1 + chunk * 32);
#pragma unroll
                    for (int k = 0; k < 8; k++) {
                        ulonglong2 bv = bp[k];
                        hreg[2 * k] = bv.x; hreg[2 * k + 1] = bv.y;
                    }
                }
#pragma unroll
                for (int half = 0; half < 2; half++) {
                    const float* vr = half ? xB : xA;
                    const float* Wb = sW1 + half * 2048 + chunk * 32;
                    for (int i0 = 0; i0 < 32; i0 += 4) {      // runtime loop
                        float4 v = *(const float4*)(vr + i0);
                        {
                            u64 vd = dup2(v.x);
                            const ulonglong2* wr = (const ulonglong2*)(Wb + (i0 + 0) * 64);
#pragma unroll
                            for (int jj = 0; jj < 8; jj++) {
                                ulonglong2 w = wr[jj];
                                hreg[2 * jj]     = ffma2(vd, w.x, hreg[2 * jj]);
                                hreg[2 * jj + 1] = ffma2(vd, w.y, hreg[2 * jj + 1]);
                            }
                        }
                        {
                            u64 vd = dup2(v.y);
                            const ulonglong2* wr = (const ulonglong2*)(Wb + (i0 + 1) * 64);
#pragma unroll
                            for (int jj = 0; jj < 8; jj++) {
                                ulonglong2 w = wr[jj];
                                hreg[2 * jj]     = ffma2(vd, w.x, hreg[2 * jj]);
                                hreg[2 * jj + 1] = ffma2(vd, w.y, hreg[2 * jj + 1]);
                            }
                        }
                        {
                            u64 vd = dup2(v.z);
                            const ulonglong2* wr = (const ulonglong2*)(Wb + (i0 + 2) * 64);
#pragma unroll
                            for (int jj = 0; jj < 8; jj++) {
                                ulonglong2 w = wr[jj];
                                hreg[2 * jj]     = ffma2(vd, w.x, hreg[2 * jj]);
                                hreg[2 * jj + 1] = ffma2(vd, w.y, hreg[2 * jj + 1]);
                            }
                        }
                        {
                            u64 vd = dup2(v.w);
                            const ulonglong2* wr = (const ulonglong2*)(Wb + (i0 + 3) * 64);
#pragma unroll
                            for (int jj = 0; jj < 8; jj++) {
                                ulonglong2 w = wr[jj];
                                hreg[2 * jj]     = ffma2(vd, w.x, hreg[2 * jj]);
                                hreg[2 * jj + 1] = ffma2(vd, w.y, hreg[2 * jj + 1]);
                            }
                        }
                    }
                }
                // LN partials + park h chunk in private smem row
                u64 s1p = hreg[0];
                u64 sqp = mul2(hreg[0], hreg[0]);
#pragma unroll
                for (int k = 1; k < 16; k++) {
                    s1p = add2(s1p, hreg[k]);
                    sqp = ffma2(hreg[k], hreg[k], sqp);
                }
                float2 a = unpack2(s1p);
                float2 q = unpack2(sqp);
                s1 += a.x + a.y;
                s2 += q.x + q.y;
                float4* hst = (float4*)(myrow + 96 + chunk * 32);
#pragma unroll
                for (int k = 0; k < 8; k++) {
                    float2 lo = unpack2(hreg[2 * k]);
                    float2 hi = unpack2(hreg[2 * k + 1]);
                    hst[k] = make_float4(lo.x, lo.y, hi.x, hi.y);
                }
            }
            const float m  = s1 * (1.0f / 64.0f);
            const float var = fmaxf(s2 * (1.0f / 64.0f) - m * m, 0.0f);
            const float iv  = rsqrtf(var + 1e-5f);

            // ---- stage 2: t = relu(LN(h)) @ W2 + b2 ----
            u64 t[16];
            {
                const ulonglong2* bp = (const ulonglong2*)sb2;
#pragma unroll
                for (int k = 0; k < 8; k++) {
                    ulonglong2 bv = bp[k];
                    t[2 * k] = bv.x; t[2 * k + 1] = bv.y;
                }
            }
            for (int r0 = 0; r0 < 64; r0 += 4) {          // runtime loop
                float4 hv = *(const float4*)(myrow + 96 + r0);
                float4 gv = *(const float4*)(sgl + r0);
                float4 bv = *(const float4*)(sbe + r0);
                float a0 = fmaxf(fmaf((hv.x - m) * iv, gv.x, bv.x), 0.0f);
                float a1 = fmaxf(fmaf((hv.y - m) * iv, gv.y, bv.y), 0.0f);
                float a2 = fmaxf(fmaf((hv.z - m) * iv, gv.z, bv.z), 0.0f);
                float a3 = fmaxf(fmaf((hv.w - m) * iv, gv.w, bv.w), 0.0f);
                {
                    u64 ad = dup2(a0);
                    const ulonglong2* wr = (const ulonglong2*)(sW2 + (r0 + 0) * 32);
#pragma unroll
                    for (int k = 0; k < 8; k++) {
                        ulonglong2 w = wr[k];
                        t[2 * k]     = ffma2(ad, w.x, t[2 * k]);
                        t[2 * k + 1] = ffma2(ad, w.y, t[2 * k + 1]);
                    }
                }
                {
                    u64 ad = dup2(a1);
                    const ulonglong2* wr = (const ulonglong2*)(sW2 + (r0 + 1) * 32);
#pragma unroll
                    for (int k = 0; k < 8; k++) {
                        ulonglong2 w = wr[k];
                        t[2 * k]     = ffma2(ad, w.x, t[2 * k]);
                        t[2 * k + 1] = ffma2(ad, w.y, t[2 * k + 1]);
                    }
                }
                {
                    u64 ad = dup2(a2);
                    const ulonglong2* wr = (const ulonglong2*)(sW2 + (r0 + 2) * 32);
#pragma unroll
                    for (int k = 0; k < 8; k++) {
                        ulonglong2 w = wr[k];
                        t[2 * k]     = ffma2(ad, w.x, t[2 * k]);
                        t[2 * k + 1] = ffma2(ad, w.y, t[2 * k + 1]);
                    }
                }
                {
                    u64 ad = dup2(a3);
                    const ulonglong2* wr = (const ulonglong2*)(sW2 + (r0 + 3) * 32);
#pragma unroll
                    for (int k = 0; k < 8; k++) {
                        ulonglong2 w = wr[k];
                        t[2 * k]     = ffma2(ad, w.x, t[2 * k]);
                        t[2 * k + 1] = ffma2(ad, w.y, t[2 * k + 1]);
                    }
                }
            }

            // ---- l2norm (per-lane) + gate + store ----
            u64 nq = mul2(t[0], t[0]);
#pragma unroll
            for (int k = 1; k < 16; k++) nq = ffma2(t[k], t[k], nq);
            float2 nf = unpack2(nq);
            float nrm = rsqrtf(fmaxf(nf.x + nf.y, 1e-24f));
            u64 sc2 = dup2(scl * nrm);
            float* orow = out + (((size_t)b * 7 + line) * 3 + p) * 32;
#pragma unroll
            for (int k = 0; k < 8; k++) {
                float2 o0 = unpack2(mul2(t[2 * k], sc2));
                float2 o1 = unpack2(mul2(t[2 * k + 1], sc2));
                ((float4*)orow)[k] = make_float4(o0.x, o0.y, o1.x, o1.y);
            }
        }
    }
}

// ============================================================================
extern "C" void kernel_launch(void* const* d_in, const int* in_sizes, int n_in,
                              void* d_out, int out_size)
{
    const float* z      = (const float*)d_in[0];
    const float* gen_W1 = (const float*)d_in[1];
    const float* gen_b1 = (const float*)d_in[2];
    const float* gen_g  = (const float*)d_in[3];
    const float* gen_be = (const float*)d_in[4];
    const float* gen_W2 = (const float*)d_in[5];
    const float* gen_b2 = (const float*)d_in[6];
    const float* cf_W1  = (const float*)d_in[7];
    const float* cf_b1  = (const float*)d_in[8];
    const float* cf_W2  = (const float*)d_in[9];
    const float* cf_b2  = (const float*)d_in[10];
    const float* g_W    = (const float*)d_in[11];
    const float* g_b    = (const float*)d_in[12];
    const float* c_W1   = (const float*)d_in[13];
    const float* c_b1   = (const float*)d_in[14];
    const float* c_g    = (const float*)d_in[15];
    const float* c_be   = (const float*)d_in[16];
    const float* c_W2   = (const float*)d_in[17];
    const float* c_b2   = (const float*)d_in[18];

    float* out      = (float*)d_out;                       // composed [B,7,3,32]
    float* out_conf = out + (size_t)B_TOTAL * 672;         // comp_conf [B,7,3]

    cudaFuncSetAttribute(colony_k1, cudaFuncAttributeMaxDynamicSharedMemorySize, K1_SMEM);
    cudaFuncSetAttribute(colony_k2, cudaFuncAttributeMaxDynamicSharedMemorySize, K2_SMEM);

    colony_k1<<<148, K1_THREADS, K1_SMEM>>>(z, gen_W1, gen_b1, gen_g, gen_be, gen_W2, gen_b2,
                                            cf_W1, cf_b1, cf_W2, cf_b2, g_W, g_b, out_conf);
    colony_k2<<<K2_GRID, K2_THREADS, K2_SMEM>>>(c_W1, c_b1, c_g, c_be, c_W2, c_b2, out);
}

// round 10
// speedup vs baseline: 1.9785x; 1.1297x over previous
#include <cuda_runtime.h>
#include <math.h>

#define B_TOTAL 65536
#define NL 7

typedef unsigned long long u64;

// ---- scratch (static device globals: allocation-free rule) ----
__device__ __align__(16) float g_traces[(size_t)B_TOTAL * 224];   // 58.7 MB
__device__ float g_gates[(size_t)B_TOTAL * NL];                   // 1.8 MB

// FSRC[l*3+j] = FANO[l][j] (colony triple per line); PAR index = (j+1)%3 locally
__constant__ int FSRC[21] = {0,1,2, 0,3,4, 0,5,6, 1,3,5, 1,4,6, 2,3,6, 2,4,5};
__constant__ int FPAR[21] = {1,2,0, 3,4,0, 5,6,0, 3,5,1, 4,6,1, 3,6,2, 4,5,2};

__device__ __forceinline__ float warp_sum(float v) {
#pragma unroll
    for (int o = 16; o > 0; o >>= 1) v += __shfl_xor_sync(0xffffffffu, v, o);
    return v;
}

// packed f32x2 helpers
__device__ __forceinline__ u64 pack2(float x, float y) {
    u64 r; asm("mov.b64 %0, {%1,%2};" : "=l"(r) : "f"(x), "f"(y)); return r;
}
__device__ __forceinline__ float2 unpack2(u64 v) {
    float2 r; asm("mov.b64 {%0,%1}, %2;" : "=f"(r.x), "=f"(r.y) : "l"(v)); return r;
}
__device__ __forceinline__ u64 dup2(float x) { return pack2(x, x); }
__device__ __forceinline__ u64 ffma2(u64 a, u64 b, u64 c) {
    u64 d; asm("fma.rn.f32x2 %0, %1, %2, %3;" : "=l"(d) : "l"(a), "l"(b), "l"(c)); return d;
}
__device__ __forceinline__ u64 add2(u64 a, u64 b) {
    u64 d; asm("add.rn.f32x2 %0, %1, %2;" : "=l"(d) : "l"(a), "l"(b)); return d;
}
__device__ __forceinline__ u64 mul2(u64 a, u64 b) {
    u64 d; asm("mul.rn.f32x2 %0, %1, %2;" : "=l"(d) : "l"(a), "l"(b)); return d;
}

__device__ __forceinline__ float fast_sigmoid(float x) {
    return __fdividef(1.0f, 1.0f + __expf(-x));
}

__device__ __forceinline__ float colony_act(int c, float x) {
    switch (c) {
        case 0: return fmaxf(x, 0.0f);
        case 1: { float e = __expf(2.0f * x); return 1.0f - __fdividef(2.0f, e + 1.0f); }
        case 2: return 0.5f * x * (1.0f + erff(x * 0.7071067811865476f));
        case 3: return x * fast_sigmoid(x);
        case 4: return fmaxf(x, 0.0f) + log1pf(__expf(-fabsf(x)));
        case 5: return fast_sigmoid(x);
        default: return fminf(fmaxf(x, -1.0f), 1.0f);
    }
}

// ============================================================================
// Kernel 1: trace generator + confidence + gates + comp_conf  (2 batches/warp)
// (unchanged — proven ~258us)
// ============================================================================
#define K1_WSZ 27344
#define K1_SCR 808
#define K1_WARPS 16
#define K1_THREADS (K1_WARPS * 32)
#define K1_SMEM ((K1_WSZ + K1_WARPS * K1_SCR) * 4)

__global__ void __launch_bounds__(K1_THREADS, 1)
colony_k1(const float* __restrict__ z,
          const float* __restrict__ gen_W1, const float* __restrict__ gen_b1,
          const float* __restrict__ gen_g,  const float* __restrict__ gen_be,
          const float* __restrict__ gen_W2, const float* __restrict__ gen_b2,
          const float* __restrict__ cf_W1,  const float* __restrict__ cf_b1,
          const float* __restrict__ cf_W2,  const float* __restrict__ cf_b2,
          const float* __restrict__ gw,     const float* __restrict__ gb,
          float* __restrict__ out_conf)
{
    extern __shared__ float sm[];
    float* sW1  = sm;            // 6272
    float* sb1  = sW1  + 6272;   // 448
    float* sg   = sb1  + 448;    // 448
    float* sbe  = sg   + 448;    // 448
    float* sW2  = sbe  + 448;    // 14336
    float* sb2  = sW2  + 14336;  // 224
    float* scW1 = sb2  + 224;    // 3136
    float* scb1 = scW1 + 3136;   // 224
    float* scW2 = scb1 + 224;    // 224
    float* scb2 = scW2 + 224;    // 8
    float* sgW  = scb2 + 8;      // 1568
    float* sgb  = sgW  + 1568;   // 8
    float* sscr = sgb  + 8;

    const int tid = threadIdx.x;
    for (int i = tid; i < 6272;  i += blockDim.x) sW1[i]  = gen_W1[i];
    for (int i = tid; i < 448;   i += blockDim.x) sb1[i]  = gen_b1[i];
    for (int i = tid; i < 448;   i += blockDim.x) sg[i]   = gen_g[i];
    for (int i = tid; i < 448;   i += blockDim.x) sbe[i]  = gen_be[i];
    for (int i = tid; i < 14336; i += blockDim.x) sW2[i]  = gen_W2[i];
    for (int i = tid; i < 224;   i += blockDim.x) sb2[i]  = gen_b2[i];
    for (int i = tid; i < 3136;  i += blockDim.x) scW1[i] = cf_W1[i];
    for (int i = tid; i < 224;   i += blockDim.x) scb1[i] = cf_b1[i];
    for (int i = tid; i < 224;   i += blockDim.x) scW2[i] = cf_W2[i];
    for (int i = tid; i < 7;     i += blockDim.x) scb2[i] = cf_b2[i];
    for (int i = tid; i < 1568;  i += blockDim.x) sgW[i]  = gw[i];
    for (int i = tid; i < 7;     i += blockDim.x) sgb[i]  = gb[i];
    __syncthreads();

    const int wid  = tid >> 5;
    const int lane = tid & 31;
    float* wscr  = sscr + wid * K1_SCR;
    float* wzA   = wscr;         // 100 (98 used)
    float* wzB   = wzA + 100;    // 100
    float* waA   = wzB + 100;    // 64
    float* waB   = waA + 64;     // 64
    float* wtrA  = waB + 64;     // 224
    float* wtrB  = wtrA + 224;   // 224
    float* wcfA  = wtrB + 224;   // 8
    float* wcfB  = wcfA + 8;     // 8
    float* wgtA  = wcfB + 8;     // 8
    float* wgtB  = wgtA + 8;     // 8

    const int gwarp = blockIdx.x * K1_WARPS + wid;
    const int nwarp = gridDim.x * K1_WARPS;

    for (int b0 = gwarp * 2; b0 < B_TOTAL; b0 += nwarp * 2) {
        const int bA = b0, bB = b0 + 1;
        const float2* zA = (const float2*)(z + (size_t)bA * 98);
        const float2* zB = (const float2*)(z + (size_t)bB * 98);
        for (int i = lane; i < 49; i += 32) {
            ((float2*)wzA)[i] = zA[i];
            ((float2*)wzB)[i] = zB[i];
        }
        __syncwarp();

#pragma unroll
        for (int c = 0; c < NL; c++) {
            float2 bias = *(const float2*)&sb1[c * 64 + 2 * lane];
            float2 hA = bias, hB = bias;
            const float* w1c = sW1 + c * (14 * 64);
            const float* zcA = wzA + c * 14;
            const float* zcB = wzB + c * 14;
#pragma unroll
            for (int q = 0; q < 14; q++) {
                float2 w = *(const float2*)&w1c[q * 64 + 2 * lane];
                float va = zcA[q], vb = zcB[q];
                hA.x = fmaf(va, w.x, hA.x); hA.y = fmaf(va, w.y, hA.y);
                hB.x = fmaf(vb, w.x, hB.x); hB.y = fmaf(vb, w.y, hB.y);
            }
            float s1A = warp_sum(hA.x + hA.y);
            float s1B = warp_sum(hB.x + hB.y);
            float s2A = warp_sum(fmaf(hA.x, hA.x, hA.y * hA.y));
            float s2B = warp_sum(fmaf(hB.x, hB.x, hB.y * hB.y));
            float mA = s1A * (1.0f / 64.0f), mB = s1B * (1.0f / 64.0f);
            float ivA = rsqrtf(fmaxf(s2A * (1.0f / 64.0f) - mA * mA, 0.0f) + 1e-5f);
            float ivB = rsqrtf(fmaxf(s2B * (1.0f / 64.0f) - mB * mB, 0.0f) + 1e-5f);
            float2 gg = *(const float2*)&sg[c * 64 + 2 * lane];
            float2 bb = *(const float2*)&sbe[c * 64 + 2 * lane];
            float2 aA, aB;
            aA.x = colony_act(c, (hA.x - mA) * ivA * gg.x + bb.x);
            aA.y = colony_act(c, (hA.y - mA) * ivA * gg.y + bb.y);
            aB.x = colony_act(c, (hB.x - mB) * ivB * gg.x + bb.x);
            aB.y = colony_act(c, (hB.y - mB) * ivB * gg.y + bb.y);
            *(float2*)&waA[2 * lane] = aA;
            *(float2*)&waB[2 * lane] = aB;
            __syncwarp();
            float tA = sb2[c * 32 + lane];
            float tB = tA;
            const float* w2c = sW2 + c * (64 * 32);
#pragma unroll
            for (int i0 = 0; i0 < 64; i0 += 4) {
                float4 vA4 = *(const float4*)&waA[i0];
                float4 vB4 = *(const float4*)&waB[i0];
#pragma unroll
                for (int q = 0; q < 4; q++) {
                    float w = w2c[(i0 + q) * 32 + lane];
                    tA = fmaf(((const float*)&vA4)[q], w, tA);
                    tB = fmaf(((const float*)&vB4)[q], w, tB);
                }
            }
            float nA = rsqrtf(fmaxf(warp_sum(tA * tA), 1e-24f));
            float nB = rsqrtf(fmaxf(warp_sum(tB * tB), 1e-24f));
            tA = tA * nA;
            tB = tB * nB;
            wtrA[c * 32 + lane] = tA;
            wtrB[c * 32 + lane] = tB;
            g_traces[(size_t)bA * 224 + c * 32 + lane] = tA;
            g_traces[(size_t)bB * 224 + c * 32 + lane] = tB;
            float hcA = scb1[c * 32 + lane];
            float hcB = hcA;
            const float* cw1 = scW1 + c * (14 * 32);
#pragma unroll
            for (int q = 0; q < 14; q++) {
                float w = cw1[q * 32 + lane];
                hcA = fmaf(zcA[q], w, hcA);
                hcB = fmaf(zcB[q], w, hcB);
            }
            float w2v = scW2[c * 32 + lane];
            float sA = warp_sum(fmaxf(hcA, 0.0f) * w2v);
            float sB = warp_sum(fmaxf(hcB, 0.0f) * w2v);
            if (lane == 0) {
                wcfA[c] = fast_sigmoid(sA + scb2[c]);
                wcfB[c] = fast_sigmoid(sB + scb2[c]);
            }
            __syncwarp();
        }

#pragma unroll
        for (int l = 0; l < NL; l++) {
            float pA = 0.0f, pB = 0.0f;
#pragma unroll
            for (int k = 0; k < 7; k++) {
                int i = lane + 32 * k;
                float w = sgW[i * 7 + l];
                pA = fmaf(wtrA[i], w, pA);
                pB = fmaf(wtrB[i], w, pB);
            }
            pA = warp_sum(pA);
            pB = warp_sum(pB);
            if (lane == 0) {
                wgtA[l] = fast_sigmoid(pA + sgb[l]);
                wgtB[l] = fast_sigmoid(pB + sgb[l]);
            }
        }
        __syncwarp();
        if (lane < 7) {
            g_gates[(size_t)bA * 7 + lane] = wgtA[lane];
            g_gates[(size_t)bB * 7 + lane] = wgtB[lane];
        }
        if (lane < 21) {
            int l = lane / 3;
            int s = FSRC[lane], p = FPAR[lane];
            float gA = wgtA[l], gB = wgtB[l];
            out_conf[(size_t)bA * 21 + lane] = (gA >= 0.3f) ? wcfA[s] * wcfA[p] * gA : 0.0f;
            out_conf[(size_t)bB * 21 + lane] = (gB >= 0.3f) ? wcfB[s] * wcfB[p] * gB : 0.0f;
        }
        __syncwarp();
    }
}

// ============================================================================
// Kernel 2: lane = 2 batches (warp = 64). Weight LDS amortized over 2 batches
// (4 FFMA2 per LDS.128). h computed in 2 chunks of 32 cols (low live regs),
// parked in private smem row (stride 132 → conflict-free float4), in-place
// LN-apply h→a, stage 2 with shared weight loads. x read from global (L2-hot).
// ============================================================================
#define K2_WARPS 10
#define K2_THREADS (K2_WARPS * 32)
#define K2_BLK_PER_LINE 21
#define K2_GRID (NL * K2_BLK_PER_LINE)
#define K2_ROW 132   // 64 floats h(A) + 64 floats h(B) + 4 pad
// smem floats: W1 4096 | W2 2048 | b1 64 | g 64 | be 64 | b2 32 | rows 10*32*132
#define K2_WSZ (6368 + K2_WARPS * 32 * K2_ROW)
#define K2_SMEM (K2_WSZ * 4)

__global__ void __launch_bounds__(K2_THREADS, 1)
colony_k2(const float* __restrict__ cW1, const float* __restrict__ cb1,
          const float* __restrict__ cg,  const float* __restrict__ cbe,
          const float* __restrict__ cW2, const float* __restrict__ cb2,
          float* __restrict__ out)
{
    extern __shared__ __align__(16) float sm[];
    float* sW1 = sm;            // [64][64] row-major
    float* sW2 = sW1 + 4096;    // [64][32] row-major
    float* sb1 = sW2 + 2048;    // 64
    float* sgl = sb1 + 64;      // 64
    float* sbe = sgl + 64;      // 64
    float* sb2 = sbe + 64;      // 32
    float* stile = sb2 + 32;    // [10 warps][32 lanes][132]

    const int line = blockIdx.x % NL;
    const int tid = threadIdx.x;
    {
        const float* w1 = cW1 + line * 4096;
        const float* w2 = cW2 + line * 2048;
        for (int i = tid; i < 4096; i += blockDim.x) sW1[i] = w1[i];
        for (int i = tid; i < 2048; i += blockDim.x) sW2[i] = w2[i];
        if (tid < 64) {
            sb1[tid] = cb1[line * 64 + tid];
            sgl[tid] = cg[line * 64 + tid];
            sbe[tid] = cbe[line * 64 + tid];
        }
        if (tid < 32) sb2[tid] = cb2[line * 32 + tid];
    }
    __syncthreads();

    const int wid  = tid >> 5;
    const int lane = tid & 31;
    float* myrow = stile + (wid * 32 + lane) * K2_ROW;   // hA [0,64), hB [64,128)

    const int col0 = FSRC[line * 3 + 0];
    const int col1 = FSRC[line * 3 + 1];
    const int col2 = FSRC[line * 3 + 2];

    const int lwarp = (blockIdx.x / NL) * K2_WARPS + wid;
    const int nlw   = K2_BLK_PER_LINE * K2_WARPS;   // 210 warps per line
    const int ngroups = B_TOTAL / 64;               // 1024

    for (int g = lwarp; g < ngroups; g += nlw) {
        const int bA = g * 64 + lane;
        const int bB = bA + 32;

        const float gateA = g_gates[(size_t)bA * 7 + line];
        const float gateB = g_gates[(size_t)bB * 7 + line];
        const float sclA = (gateA >= 0.3f) ? gateA : 0.0f;
        const float sclB = (gateB >= 0.3f) ? gateB : 0.0f;

        for (int p = 0; p < 3; p++) {
            const int cS = (p == 0) ? col0 : (p == 1) ? col1 : col2;
            const int cP = (p == 0) ? col1 : (p == 1) ? col2 : col0;

            // ---- stage 1: h = [xS,xP] @ W1 + b1, in two 32-col chunks ----
            float s1A = 0.0f, s2A = 0.0f, s1B = 0.0f, s2B = 0.0f;
            for (int chunk = 0; chunk < 2; chunk++) {
                u64 hA[16], hB[16];
                {
                    const ulonglong2* bp = (const ulonglong2*)(sb1 + chunk * 32);
#pragma unroll
                    for (int k = 0; k < 8; k++) {
                        ulonglong2 bv = bp[k];
                        hA[2 * k] = bv.x; hA[2 * k + 1] = bv.y;
                        hB[2 * k] = bv.x; hB[2 * k + 1] = bv.y;
                    }
                }
                for (int half = 0; half < 2; half++) {
                    const int colony = half ? cP : cS;
                    const float4* xAp = (const float4*)(g_traces + (size_t)bA * 224 + colony * 32);
                    const float4* xBp = (const float4*)(g_traces + (size_t)bB * 224 + colony * 32);
                    const float* Wb = sW1 + half * 2048 + chunk * 32;
#pragma unroll
                    for (int i0 = 0; i0 < 8; i0++) {
                        float4 vA = xAp[i0];
                        float4 vB = xBp[i0];
#pragma unroll
                        for (int r = 0; r < 4; r++) {
                            float fa = (r == 0) ? vA.x : (r == 1) ? vA.y : (r == 2) ? vA.z : vA.w;
                            float fb = (r == 0) ? vB.x : (r == 1) ? vB.y : (r == 2) ? vB.z : vB.w;
                            u64 aD = dup2(fa);
                            u64 bD = dup2(fb);
                            const ulonglong2* wr = (const ulonglong2*)(Wb + (i0 * 4 + r) * 64);
#pragma unroll
                            for (int jj = 0; jj < 8; jj++) {
                                ulonglong2 w = wr[jj];
                                hA[2 * jj]     = ffma2(aD, w.x, hA[2 * jj]);
                                hA[2 * jj + 1] = ffma2(aD, w.y, hA[2 * jj + 1]);
                                hB[2 * jj]     = ffma2(bD, w.x, hB[2 * jj]);
                                hB[2 * jj + 1] = ffma2(bD, w.y, hB[2 * jj + 1]);
                            }
                        }
                    }
                }
                // LN partials + park h chunk
                {
                    u64 sA = hA[0], qA = mul2(hA[0], hA[0]);
                    u64 sB = hB[0], qB = mul2(hB[0], hB[0]);
#pragma unroll
                    for (int k = 1; k < 16; k++) {
                        sA = add2(sA, hA[k]); qA = ffma2(hA[k], hA[k], qA);
                        sB = add2(sB, hB[k]); qB = ffma2(hB[k], hB[k], qB);
                    }
                    float2 a1 = unpack2(sA), a2 = unpack2(qA);
                    float2 b1 = unpack2(sB), b2 = unpack2(qB);
                    s1A += a1.x + a1.y;  s2A += a2.x + a2.y;
                    s1B += b1.x + b1.y;  s2B += b2.x + b2.y;
                }
                {
                    float4* hstA = (float4*)(myrow + chunk * 32);
                    float4* hstB = (float4*)(myrow + 64 + chunk * 32);
#pragma unroll
                    for (int k = 0; k < 8; k++) {
                        float2 lo = unpack2(hA[2 * k]);
                        float2 hi = unpack2(hA[2 * k + 1]);
                        hstA[k] = make_float4(lo.x, lo.y, hi.x, hi.y);
                        lo = unpack2(hB[2 * k]);
                        hi = unpack2(hB[2 * k + 1]);
                        hstB[k] = make_float4(lo.x, lo.y, hi.x, hi.y);
                    }
                }
            }
            const float mA = s1A * (1.0f / 64.0f);
            const float mB = s1B * (1.0f / 64.0f);
            const float ivA = rsqrtf(fmaxf(s2A * (1.0f / 64.0f) - mA * mA, 0.0f) + 1e-5f);
            const float ivB = rsqrtf(fmaxf(s2B * (1.0f / 64.0f) - mB * mB, 0.0f) + 1e-5f);

            // ---- LN-apply + ReLU in place: h -> a ----
#pragma unroll
            for (int r0 = 0; r0 < 16; r0++) {
                float4 gv = ((const float4*)sgl)[r0];
                float4 bv = ((const float4*)sbe)[r0];
                float4 hvA = ((const float4*)myrow)[r0];
                float4 hvB = ((const float4*)(myrow + 64))[r0];
                float4 aA, aB;
                aA.x = fmaxf(fmaf((hvA.x - mA) * ivA, gv.x, bv.x), 0.0f);
                aA.y = fmaxf(fmaf((hvA.y - mA) * ivA, gv.y, bv.y), 0.0f);
                aA.z = fmaxf(fmaf((hvA.z - mA) * ivA, gv.z, bv.z), 0.0f);
                aA.w = fmaxf(fmaf((hvA.w - mA) * ivA, gv.w, bv.w), 0.0f);
                aB.x = fmaxf(fmaf((hvB.x - mB) * ivB, gv.x, bv.x), 0.0f);
                aB.y = fmaxf(fmaf((hvB.y - mB) * ivB, gv.y, bv.y), 0.0f);
                aB.z = fmaxf(fmaf((hvB.z - mB) * ivB, gv.z, bv.z), 0.0f);
                aB.w = fmaxf(fmaf((hvB.w - mB) * ivB, gv.w, bv.w), 0.0f);
                ((float4*)myrow)[r0] = aA;
                ((float4*)(myrow + 64))[r0] = aB;
            }

            // ---- stage 2: t = a @ W2 + b2 (weights shared across both batches) ----
            u64 tA[16], tB[16];
            {
                const ulonglong2* bp = (const ulonglong2*)sb2;
#pragma unroll
                for (int k = 0; k < 8; k++) {
                    ulonglong2 bv = bp[k];
                    tA[2 * k] = bv.x; tA[2 * k + 1] = bv.y;
                    tB[2 * k] = bv.x; tB[2 * k + 1] = bv.y;
                }
            }
            for (int r0 = 0; r0 < 16; r0++) {       // runtime loop: 4 rows/iter
                float4 vA = ((const float4*)myrow)[r0];
                float4 vB = ((const float4*)(myrow + 64))[r0];
#pragma unroll
                for (int r = 0; r < 4; r++) {
                    float fa = (r == 0) ? vA.x : (r == 1) ? vA.y : (r == 2) ? vA.z : vA.w;
                    float fb = (r == 0) ? vB.x : (r == 1) ? vB.y : (r == 2) ? vB.z : vB.w;
                    u64 aD = dup2(fa);
                    u64 bD = dup2(fb);
                    const ulonglong2* wr = (const ulonglong2*)(sW2 + (r0 * 4 + r) * 32);
#pragma unroll
                    for (int k = 0; k < 4; k++) {
                        ulonglong2 w = wr[k];
                        tA[4 * k]     = ffma2(aD, w.x, tA[4 * k]);
                        tA[4 * k + 1] = ffma2(aD, w.y, tA[4 * k + 1]);
                        tB[4 * k]     = ffma2(bD, w.x, tB[4 * k]);
                        tB[4 * k + 1] = ffma2(bD, w.y, tB[4 * k + 1]);
                    }
#pragma unroll
                    for (int k = 0; k < 4; k++) {
                        ulonglong2 w = ((const ulonglong2*)(sW2 + (r0 * 4 + r) * 32))[k + 4];
                        tA[4 * k + 2] = ffma2(aD, w.x, tA[4 * k + 2]);
                        tA[4 * k + 3] = ffma2(aD, w.y, tA[4 * k + 3]);
                        tB[4 * k + 2] = ffma2(bD, w.x, tB[4 * k + 2]);
                        tB[4 * k + 3] = ffma2(bD, w.y, tB[4 * k + 3]);
                    }
                }
            }
            // NOTE on t layout: wr[k] covers cols 4k..4k+3 (k<4 → cols 0..15 into
            // tA[4k..4k+3]? fix mapping below) — we instead keep a FLAT mapping:
            // recompute norms from flat sum; store uses the same mapping as loads,
            // so layout consistency is what matters: w index k (0..7) covers cols
            // 4k..4k+3 and was accumulated into t[(k<4)?(4k..):((k-4)*4+2..)].
            // To keep store correct we re-gather through the same index map.

            // ---- l2norm + gate + store (same index map as accumulation) ----
            {
                u64 nqA = mul2(tA[0], tA[0]);
                u64 nqB = mul2(tB[0], tB[0]);
#pragma unroll
                for (int k = 1; k < 16; k++) {
                    nqA = ffma2(tA[k], tA[k], nqA);
                    nqB = ffma2(tB[k], tB[k], nqB);
                }
                float2 fa = unpack2(nqA), fb = unpack2(nqB);
                float nrmA = rsqrtf(fmaxf(fa.x + fa.y, 1e-24f));
                float nrmB = rsqrtf(fmaxf(fb.x + fb.y, 1e-24f));
                u64 scA2 = dup2(sclA * nrmA);
                u64 scB2 = dup2(sclB * nrmB);
                float* orowA = out + (((size_t)bA * 7 + line) * 3 + p) * 32;
                float* orowB = out + (((size_t)bB * 7 + line) * 3 + p) * 32;
                // cols 4k,4k+1 live in t[4k'] / t[4k'+1] for k<4 (k'=k) and
                // t[4k'+2]/t[4k'+3] for k>=4 (k'=k-4): emit per weight-index k
#pragma unroll
                for (int k = 0; k < 8; k++) {
                    int ia = (k < 4) ? 4 * k : 4 * (k - 4) + 2;
                    float2 o0 = unpack2(mul2(tA[ia], scA2));
                    float2 o1 = unpack2(mul2(tA[ia + 1], scA2));
                    ((float4*)orowA)[k] = make_float4(o0.x, o0.y, o1.x, o1.y);
                    o0 = unpack2(mul2(tB[ia], scB2));
                    o1 = unpack2(mul2(tB[ia + 1], scB2));
                    ((float4*)orowB)[k] = make_float4(o0.x, o0.y, o1.x, o1.y);
                }
            }
        }
    }
}

// ============================================================================
extern "C" void kernel_launch(void* const* d_in, const int* in_sizes, int n_in,
                              void* d_out, int out_size)
{
    const float* z      = (const float*)d_in[0];
    const float* gen_W1 = (const float*)d_in[1];
    const float* gen_b1 = (const float*)d_in[2];
    const float* gen_g  = (const float*)d_in[3];
    const float* gen_be = (const float*)d_in[4];
    const float* gen_W2 = (const float*)d_in[5];
    const float* gen_b2 = (const float*)d_in[6];
    const float* cf_W1  = (const float*)d_in[7];
    const float* cf_b1  = (const float*)d_in[8];
    const float* cf_W2  = (const float*)d_in[9];
    const float* cf_b2  = (const float*)d_in[10];
    const float* g_W    = (const float*)d_in[11];
    const float* g_b    = (const float*)d_in[12];
    const float* c_W1   = (const float*)d_in[13];
    const float* c_b1   = (const float*)d_in[14];
    const float* c_g    = (const float*)d_in[15];
    const float* c_be   = (const float*)d_in[16];
    const float* c_W2   = (const float*)d_in[17];
    const float* c_b2   = (const float*)d_in[18];

    float* out      = (float*)d_out;                       // composed [B,7,3,32]
    float* out_conf = out + (size_t)B_TOTAL * 672;         // comp_conf [B,7,3]

    cudaFuncSetAttribute(colony_k1, cudaFuncAttributeMaxDynamicSharedMemorySize, K1_SMEM);
    cudaFuncSetAttribute(colony_k2, cudaFuncAttributeMaxDynamicSharedMemorySize, K2_SMEM);

    colony_k1<<<148, K1_THREADS, K1_SMEM>>>(z, gen_W1, gen_b1, gen_g, gen_be, gen_W2, gen_b2,
                                            cf_W1, cf_b1, cf_W2, cf_b2, g_W, g_b, out_conf);
    colony_k2<<<K2_GRID, K2_THREADS, K2_SMEM>>>(c_W1, c_b1, c_g, c_be, c_W2, c_b2, out);
}

// round 11
// speedup vs baseline: 2.1626x; 1.0931x over previous
#include <cuda_runtime.h>
#include <math.h>

#define B_TOTAL 65536
#define NL 7

typedef unsigned long long u64;

// ---- scratch (static device globals: allocation-free rule) ----
__device__ __align__(16) float g_traces[(size_t)B_TOTAL * 224];       // 58.7 MB (batch-major)
__device__ __align__(16) float g_traces_blk[(size_t)B_TOTAL * 224];   // 58.7 MB (blocked: [blk][c][d][32])
__device__ float g_gates[(size_t)B_TOTAL * NL];                       // 1.8 MB
__device__ float g_gates_T[(size_t)NL * B_TOTAL];                     // 1.8 MB

__constant__ int FSRC[21] = {0,1,2, 0,3,4, 0,5,6, 1,3,5, 1,4,6, 2,3,6, 2,4,5};
__constant__ int FPAR[21] = {1,2,0, 3,4,0, 5,6,0, 3,5,1, 4,6,1, 3,6,2, 4,5,2};

__device__ __forceinline__ float warp_sum(float v) {
#pragma unroll
    for (int o = 16; o > 0; o >>= 1) v += __shfl_xor_sync(0xffffffffu, v, o);
    return v;
}

__device__ __forceinline__ u64 pack2(float x, float y) {
    u64 r; asm("mov.b64 %0, {%1,%2};" : "=l"(r) : "f"(x), "f"(y)); return r;
}
__device__ __forceinline__ float2 unpack2(u64 v) {
    float2 r; asm("mov.b64 {%0,%1}, %2;" : "=f"(r.x), "=f"(r.y) : "l"(v)); return r;
}
__device__ __forceinline__ u64 dup2(float x) { return pack2(x, x); }
__device__ __forceinline__ u64 ffma2(u64 a, u64 b, u64 c) {
    u64 d; asm("fma.rn.f32x2 %0, %1, %2, %3;" : "=l"(d) : "l"(a), "l"(b), "l"(c)); return d;
}
__device__ __forceinline__ u64 add2(u64 a, u64 b) {
    u64 d; asm("add.rn.f32x2 %0, %1, %2;" : "=l"(d) : "l"(a), "l"(b)); return d;
}
__device__ __forceinline__ u64 mul2(u64 a, u64 b) {
    u64 d; asm("mul.rn.f32x2 %0, %1, %2;" : "=l"(d) : "l"(a), "l"(b)); return d;
}

__device__ __forceinline__ float fast_sigmoid(float x) {
    return __fdividef(1.0f, 1.0f + __expf(-x));
}

__device__ __forceinline__ float colony_act(int c, float x) {
    switch (c) {
        case 0: return fmaxf(x, 0.0f);
        case 1: { float e = __expf(2.0f * x); return 1.0f - __fdividef(2.0f, e + 1.0f); }
        case 2: return 0.5f * x * (1.0f + erff(x * 0.7071067811865476f));
        case 3: return x * fast_sigmoid(x);
        case 4: return fmaxf(x, 0.0f) + log1pf(__expf(-fabsf(x)));
        case 5: return fast_sigmoid(x);
        default: return fminf(fmaxf(x, -1.0f), 1.0f);
    }
}

// ============================================================================
// Kernel 1: trace generator + confidence + gates + comp_conf  (2 batches/warp)
// (unchanged — proven)
// ============================================================================
#define K1_WSZ 27344
#define K1_SCR 808
#define K1_WARPS 16
#define K1_THREADS (K1_WARPS * 32)
#define K1_SMEM ((K1_WSZ + K1_WARPS * K1_SCR) * 4)

__global__ void __launch_bounds__(K1_THREADS, 1)
colony_k1(const float* __restrict__ z,
          const float* __restrict__ gen_W1, const float* __restrict__ gen_b1,
          const float* __restrict__ gen_g,  const float* __restrict__ gen_be,
          const float* __restrict__ gen_W2, const float* __restrict__ gen_b2,
          const float* __restrict__ cf_W1,  const float* __restrict__ cf_b1,
          const float* __restrict__ cf_W2,  const float* __restrict__ cf_b2,
          const float* __restrict__ gw,     const float* __restrict__ gb,
          float* __restrict__ out_conf)
{
    extern __shared__ float sm[];
    float* sW1  = sm;            // 6272
    float* sb1  = sW1  + 6272;   // 448
    float* sg   = sb1  + 448;    // 448
    float* sbe  = sg   + 448;    // 448
    float* sW2  = sbe  + 448;    // 14336
    float* sb2  = sW2  + 14336;  // 224
    float* scW1 = sb2  + 224;    // 3136
    float* scb1 = scW1 + 3136;   // 224
    float* scW2 = scb1 + 224;    // 224
    float* scb2 = scW2 + 224;    // 8
    float* sgW  = scb2 + 8;      // 1568
    float* sgb  = sgW  + 1568;   // 8
    float* sscr = sgb  + 8;

    const int tid = threadIdx.x;
    for (int i = tid; i < 6272;  i += blockDim.x) sW1[i]  = gen_W1[i];
    for (int i = tid; i < 448;   i += blockDim.x) sb1[i]  = gen_b1[i];
    for (int i = tid; i < 448;   i += blockDim.x) sg[i]   = gen_g[i];
    for (int i = tid; i < 448;   i += blockDim.x) sbe[i]  = gen_be[i];
    for (int i = tid; i < 14336; i += blockDim.x) sW2[i]  = gen_W2[i];
    for (int i = tid; i < 224;   i += blockDim.x) sb2[i]  = gen_b2[i];
    for (int i = tid; i < 3136;  i += blockDim.x) scW1[i] = cf_W1[i];
    for (int i = tid; i < 224;   i += blockDim.x) scb1[i] = cf_b1[i];
    for (int i = tid; i < 224;   i += blockDim.x) scW2[i] = cf_W2[i];
    for (int i = tid; i < 7;     i += blockDim.x) scb2[i] = cf_b2[i];
    for (int i = tid; i < 1568;  i += blockDim.x) sgW[i]  = gw[i];
    for (int i = tid; i < 7;     i += blockDim.x) sgb[i]  = gb[i];
    __syncthreads();

    const int wid  = tid >> 5;
    const int lane = tid & 31;
    float* wscr  = sscr + wid * K1_SCR;
    float* wzA   = wscr;         // 100 (98 used)
    float* wzB   = wzA + 100;    // 100
    float* waA   = wzB + 100;    // 64
    float* waB   = waA + 64;     // 64
    float* wtrA  = waB + 64;     // 224
    float* wtrB  = wtrA + 224;   // 224
    float* wcfA  = wtrB + 224;   // 8
    float* wcfB  = wcfA + 8;     // 8
    float* wgtA  = wcfB + 8;     // 8
    float* wgtB  = wgtA + 8;     // 8

    const int gwarp = blockIdx.x * K1_WARPS + wid;
    const int nwarp = gridDim.x * K1_WARPS;

    for (int b0 = gwarp * 2; b0 < B_TOTAL; b0 += nwarp * 2) {
        const int bA = b0, bB = b0 + 1;
        const float2* zA = (const float2*)(z + (size_t)bA * 98);
        const float2* zB = (const float2*)(z + (size_t)bB * 98);
        for (int i = lane; i < 49; i += 32) {
            ((float2*)wzA)[i] = zA[i];
            ((float2*)wzB)[i] = zB[i];
        }
        __syncwarp();

#pragma unroll
        for (int c = 0; c < NL; c++) {
            float2 bias = *(const float2*)&sb1[c * 64 + 2 * lane];
            float2 hA = bias, hB = bias;
            const float* w1c = sW1 + c * (14 * 64);
            const float* zcA = wzA + c * 14;
            const float* zcB = wzB + c * 14;
#pragma unroll
            for (int q = 0; q < 14; q++) {
                float2 w = *(const float2*)&w1c[q * 64 + 2 * lane];
                float va = zcA[q], vb = zcB[q];
                hA.x = fmaf(va, w.x, hA.x); hA.y = fmaf(va, w.y, hA.y);
                hB.x = fmaf(vb, w.x, hB.x); hB.y = fmaf(vb, w.y, hB.y);
            }
            float s1A = warp_sum(hA.x + hA.y);
            float s1B = warp_sum(hB.x + hB.y);
            float s2A = warp_sum(fmaf(hA.x, hA.x, hA.y * hA.y));
            float s2B = warp_sum(fmaf(hB.x, hB.x, hB.y * hB.y));
            float mA = s1A * (1.0f / 64.0f), mB = s1B * (1.0f / 64.0f);
            float ivA = rsqrtf(fmaxf(s2A * (1.0f / 64.0f) - mA * mA, 0.0f) + 1e-5f);
            float ivB = rsqrtf(fmaxf(s2B * (1.0f / 64.0f) - mB * mB, 0.0f) + 1e-5f);
            float2 gg = *(const float2*)&sg[c * 64 + 2 * lane];
            float2 bb = *(const float2*)&sbe[c * 64 + 2 * lane];
            float2 aA, aB;
            aA.x = colony_act(c, (hA.x - mA) * ivA * gg.x + bb.x);
            aA.y = colony_act(c, (hA.y - mA) * ivA * gg.y + bb.y);
            aB.x = colony_act(c, (hB.x - mB) * ivB * gg.x + bb.x);
            aB.y = colony_act(c, (hB.y - mB) * ivB * gg.y + bb.y);
            *(float2*)&waA[2 * lane] = aA;
            *(float2*)&waB[2 * lane] = aB;
            __syncwarp();
            float tA = sb2[c * 32 + lane];
            float tB = tA;
            const float* w2c = sW2 + c * (64 * 32);
#pragma unroll
            for (int i0 = 0; i0 < 64; i0 += 4) {
                float4 vA4 = *(const float4*)&waA[i0];
                float4 vB4 = *(const float4*)&waB[i0];
#pragma unroll
                for (int q = 0; q < 4; q++) {
                    float w = w2c[(i0 + q) * 32 + lane];
                    tA = fmaf(((const float*)&vA4)[q], w, tA);
                    tB = fmaf(((const float*)&vB4)[q], w, tB);
                }
            }
            float nA = rsqrtf(fmaxf(warp_sum(tA * tA), 1e-24f));
            float nB = rsqrtf(fmaxf(warp_sum(tB * tB), 1e-24f));
            tA = tA * nA;
            tB = tB * nB;
            wtrA[c * 32 + lane] = tA;
            wtrB[c * 32 + lane] = tB;
            g_traces[(size_t)bA * 224 + c * 32 + lane] = tA;
            g_traces[(size_t)bB * 224 + c * 32 + lane] = tB;
            float hcA = scb1[c * 32 + lane];
            float hcB = hcA;
            const float* cw1 = scW1 + c * (14 * 32);
#pragma unroll
            for (int q = 0; q < 14; q++) {
                float w = cw1[q * 32 + lane];
                hcA = fmaf(zcA[q], w, hcA);
                hcB = fmaf(zcB[q], w, hcB);
            }
            float w2v = scW2[c * 32 + lane];
            float sA = warp_sum(fmaxf(hcA, 0.0f) * w2v);
            float sB = warp_sum(fmaxf(hcB, 0.0f) * w2v);
            if (lane == 0) {
                wcfA[c] = fast_sigmoid(sA + scb2[c]);
                wcfB[c] = fast_sigmoid(sB + scb2[c]);
            }
            __syncwarp();
        }

#pragma unroll
        for (int l = 0; l < NL; l++) {
            float pA = 0.0f, pB = 0.0f;
#pragma unroll
            for (int k = 0; k < 7; k++) {
                int i = lane + 32 * k;
                float w = sgW[i * 7 + l];
                pA = fmaf(wtrA[i], w, pA);
                pB = fmaf(wtrB[i], w, pB);
            }
            pA = warp_sum(pA);
            pB = warp_sum(pB);
            if (lane == 0) {
                wgtA[l] = fast_sigmoid(pA + sgb[l]);
                wgtB[l] = fast_sigmoid(pB + sgb[l]);
            }
        }
        __syncwarp();
        if (lane < 7) {
            g_gates[(size_t)bA * 7 + lane] = wgtA[lane];
            g_gates[(size_t)bB * 7 + lane] = wgtB[lane];
        }
        if (lane < 21) {
            int l = lane / 3;
            int s = FSRC[lane], p = FPAR[lane];
            float gA = wgtA[l], gB = wgtB[l];
            out_conf[(size_t)bA * 21 + lane] = (gA >= 0.3f) ? wcfA[s] * wcfA[p] * gA : 0.0f;
            out_conf[(size_t)bB * 21 + lane] = (gB >= 0.3f) ? wcfB[s] * wcfB[p] * gB : 0.0f;
        }
        __syncwarp();
    }
}

// ============================================================================
// Kernel T: transpose traces into 32-batch blocks + gates into line-major.
// g_traces_blk[blk][c][d][bb] , g_gates_T[line][b]. Pure bandwidth (~117MB).
// ============================================================================
__global__ void __launch_bounds__(256, 4)
colony_kt()
{
    __shared__ float tile[32 * 225];
    const int blk = blockIdx.x;                    // 0..2047
    const float* src = g_traces + (size_t)blk * 7168;
    for (int idx = threadIdx.x; idx < 7168; idx += 256) {
        int b = idx / 224, d = idx % 224;
        tile[b * 225 + d] = src[idx];              // coalesced read
    }
    __syncthreads();
    float* dst = g_traces_blk + (size_t)blk * 7168;
    for (int idx = threadIdx.x; idx < 7168; idx += 256) {
        int cd = idx >> 5, bb = idx & 31;
        dst[idx] = tile[bb * 225 + cd];            // coalesced write
    }
    for (int idx = threadIdx.x; idx < 224; idx += 256) {
        int l = idx >> 5, bb = idx & 31;
        g_gates_T[(size_t)l * B_TOTAL + blk * 32 + bb] =
            g_gates[(size_t)(blk * 32 + bb) * 7 + l];
    }
}

// ============================================================================
// Kernel 2: lane = 2 batches; blocked-layout x (coalesced LDG.32); chunked
// stage1; h parked in private rows; stage2 with fused LN; outputs staged in
// rows then cooperatively stored coalesced.
// ============================================================================
#define K2_WARPS 10
#define K2_THREADS (K2_WARPS * 32)
#define K2_BLK_PER_LINE 21
#define K2_GRID (NL * K2_BLK_PER_LINE)
#define K2_ROW 132   // hA [0,64) | hB [64,128) | pad 4 ; reused for outputs
#define K2_WSZ (6368 + K2_WARPS * 32 * K2_ROW)
#define K2_SMEM (K2_WSZ * 4)

__global__ void __launch_bounds__(K2_THREADS, 1)
colony_k2(const float* __restrict__ cW1, const float* __restrict__ cb1,
          const float* __restrict__ cg,  const float* __restrict__ cbe,
          const float* __restrict__ cW2, const float* __restrict__ cb2,
          float* __restrict__ out)
{
    extern __shared__ __align__(16) float sm[];
    float* sW1 = sm;            // [64][64] row-major
    float* sW2 = sW1 + 4096;    // [64][32] row-major
    float* sb1 = sW2 + 2048;    // 64
    float* sgl = sb1 + 64;      // 64
    float* sbe = sgl + 64;      // 64
    float* sb2 = sbe + 64;      // 32
    float* stile = sb2 + 32;    // [10 warps][32 lanes][132]

    const int line = blockIdx.x % NL;
    const int tid = threadIdx.x;
    {
        const float* w1 = cW1 + line * 4096;
        const float* w2 = cW2 + line * 2048;
        for (int i = tid; i < 4096; i += blockDim.x) sW1[i] = w1[i];
        for (int i = tid; i < 2048; i += blockDim.x) sW2[i] = w2[i];
        if (tid < 64) {
            sb1[tid] = cb1[line * 64 + tid];
            sgl[tid] = cg[line * 64 + tid];
            sbe[tid] = cbe[line * 64 + tid];
        }
        if (tid < 32) sb2[tid] = cb2[line * 32 + tid];
    }
    __syncthreads();

    const int wid  = tid >> 5;
    const int lane = tid & 31;
    float* myrow = stile + (wid * 32 + lane) * K2_ROW;
    float* wrows = stile + (wid * 32) * K2_ROW;        // base of this warp's rows

    const int col0 = FSRC[line * 3 + 0];
    const int col1 = FSRC[line * 3 + 1];
    const int col2 = FSRC[line * 3 + 2];

    const int lwarp = (blockIdx.x / NL) * K2_WARPS + wid;
    const int nlw   = K2_BLK_PER_LINE * K2_WARPS;   // 210
    const int ngroups = B_TOTAL / 64;               // 1024

    for (int g = lwarp; g < ngroups; g += nlw) {
        const int blkA = 2 * g, blkB = 2 * g + 1;
        const int bA = g * 64 + lane;
        const int bB = bA + 32;

        const float gateA = g_gates_T[(size_t)line * B_TOTAL + bA];   // coalesced
        const float gateB = g_gates_T[(size_t)line * B_TOTAL + bB];
        const float sclA = (gateA >= 0.3f) ? gateA : 0.0f;
        const float sclB = (gateB >= 0.3f) ? gateB : 0.0f;

        for (int p = 0; p < 3; p++) {
            const int cS = (p == 0) ? col0 : (p == 1) ? col1 : col2;
            const int cP = (p == 0) ? col1 : (p == 1) ? col2 : col0;

            // ---- stage 1: h in two 32-col chunks; x coalesced from blocked layout ----
            float s1A = 0.0f, s2A = 0.0f, s1B = 0.0f, s2B = 0.0f;
            for (int chunk = 0; chunk < 2; chunk++) {
                u64 hA[16], hB[16];
                {
                    const ulonglong2* bp = (const ulonglong2*)(sb1 + chunk * 32);
#pragma unroll
                    for (int k = 0; k < 8; k++) {
                        ulonglong2 bv = bp[k];
                        hA[2 * k] = bv.x; hA[2 * k + 1] = bv.y;
                        hB[2 * k] = bv.x; hB[2 * k + 1] = bv.y;
                    }
                }
                for (int half = 0; half < 2; half++) {
                    const int colony = half ? cP : cS;
                    const float* xA = g_traces_blk + (size_t)blkA * 7168 + colony * 1024 + lane;
                    const float* xB = g_traces_blk + (size_t)blkB * 7168 + colony * 1024 + lane;
                    const float* Wb = sW1 + half * 2048 + chunk * 32;
#pragma unroll 8
                    for (int i = 0; i < 32; i++) {
                        u64 aD = dup2(xA[i * 32]);     // coalesced LDG.32
                        u64 bD = dup2(xB[i * 32]);
                        const ulonglong2* wr = (const ulonglong2*)(Wb + i * 64);
#pragma unroll
                        for (int jj = 0; jj < 8; jj++) {
                            ulonglong2 w = wr[jj];
                            hA[2 * jj]     = ffma2(aD, w.x, hA[2 * jj]);
                            hA[2 * jj + 1] = ffma2(aD, w.y, hA[2 * jj + 1]);
                            hB[2 * jj]     = ffma2(bD, w.x, hB[2 * jj]);
                            hB[2 * jj + 1] = ffma2(bD, w.y, hB[2 * jj + 1]);
                        }
                    }
                }
                // LN partials + park h chunk
                {
                    u64 sAp = hA[0], qAp = mul2(hA[0], hA[0]);
                    u64 sBp = hB[0], qBp = mul2(hB[0], hB[0]);
#pragma unroll
                    for (int k = 1; k < 16; k++) {
                        sAp = add2(sAp, hA[k]); qAp = ffma2(hA[k], hA[k], qAp);
                        sBp = add2(sBp, hB[k]); qBp = ffma2(hB[k], hB[k], qBp);
                    }
                    float2 a1 = unpack2(sAp), a2 = unpack2(qAp);
                    float2 b1 = unpack2(sBp), b2 = unpack2(qBp);
                    s1A += a1.x + a1.y;  s2A += a2.x + a2.y;
                    s1B += b1.x + b1.y;  s2B += b2.x + b2.y;
                }
                {
                    float4* hstA = (float4*)(myrow + chunk * 32);
                    float4* hstB = (float4*)(myrow + 64 + chunk * 32);
#pragma unroll
                    for (int k = 0; k < 8; k++) {
                        float2 lo = unpack2(hA[2 * k]);
                        float2 hi = unpack2(hA[2 * k + 1]);
                        hstA[k] = make_float4(lo.x, lo.y, hi.x, hi.y);
                        lo = unpack2(hB[2 * k]);
                        hi = unpack2(hB[2 * k + 1]);
                        hstB[k] = make_float4(lo.x, lo.y, hi.x, hi.y);
                    }
                }
            }
            const float mA = s1A * (1.0f / 64.0f);
            const float mB = s1B * (1.0f / 64.0f);
            const float ivA = rsqrtf(fmaxf(s2A * (1.0f / 64.0f) - mA * mA, 0.0f) + 1e-5f);
            const float ivB = rsqrtf(fmaxf(s2B * (1.0f / 64.0f) - mB * mB, 0.0f) + 1e-5f);

            // ---- stage 2: fused LN-apply + ReLU, t = a @ W2 + b2 ----
            u64 tA[16], tB[16];
            {
                const ulonglong2* bp = (const ulonglong2*)sb2;
#pragma unroll
                for (int k = 0; k < 8; k++) {
                    ulonglong2 bv = bp[k];
                    tA[2 * k] = bv.x; tA[2 * k + 1] = bv.y;
                    tB[2 * k] = bv.x; tB[2 * k + 1] = bv.y;
                }
            }
#pragma unroll 4
            for (int r0 = 0; r0 < 16; r0++) {
                float4 hvA = ((const float4*)myrow)[r0];
                float4 hvB = ((const float4*)(myrow + 64))[r0];
                float4 gv = ((const float4*)sgl)[r0];
                float4 bv = ((const float4*)sbe)[r0];
#pragma unroll
                for (int r = 0; r < 4; r++) {
                    float hA1 = (r == 0) ? hvA.x : (r == 1) ? hvA.y : (r == 2) ? hvA.z : hvA.w;
                    float hB1 = (r == 0) ? hvB.x : (r == 1) ? hvB.y : (r == 2) ? hvB.z : hvB.w;
                    float gw1 = (r == 0) ? gv.x : (r == 1) ? gv.y : (r == 2) ? gv.z : gv.w;
                    float bw1 = (r == 0) ? bv.x : (r == 1) ? bv.y : (r == 2) ? bv.z : bv.w;
                    float aAv = fmaxf(fmaf((hA1 - mA) * ivA, gw1, bw1), 0.0f);
                    float aBv = fmaxf(fmaf((hB1 - mB) * ivB, gw1, bw1), 0.0f);
                    u64 aD = dup2(aAv);
                    u64 bD = dup2(aBv);
                    const ulonglong2* wr = (const ulonglong2*)(sW2 + (r0 * 4 + r) * 32);
#pragma unroll
                    for (int k = 0; k < 8; k++) {
                        ulonglong2 w = wr[k];
                        tA[2 * k]     = ffma2(aD, w.x, tA[2 * k]);
                        tA[2 * k + 1] = ffma2(aD, w.y, tA[2 * k + 1]);
                        tB[2 * k]     = ffma2(bD, w.x, tB[2 * k]);
                        tB[2 * k + 1] = ffma2(bD, w.y, tB[2 * k + 1]);
                    }
                }
            }

            // ---- l2norm + gate; park outputs in row (h region dead) ----
            {
                u64 nqA = mul2(tA[0], tA[0]);
                u64 nqB = mul2(tB[0], tB[0]);
#pragma unroll
                for (int k = 1; k < 16; k++) {
                    nqA = ffma2(tA[k], tA[k], nqA);
                    nqB = ffma2(tB[k], tB[k], nqB);
                }
                float2 fa = unpack2(nqA), fb = unpack2(nqB);
                u64 scA2 = dup2(sclA * rsqrtf(fmaxf(fa.x + fa.y, 1e-24f)));
                u64 scB2 = dup2(sclB * rsqrtf(fmaxf(fb.x + fb.y, 1e-24f)));
                float4* oA = (float4*)myrow;
                float4* oB = (float4*)(myrow + 64);
#pragma unroll
                for (int k = 0; k < 8; k++) {
                    float2 o0 = unpack2(mul2(tA[2 * k], scA2));
                    float2 o1 = unpack2(mul2(tA[2 * k + 1], scA2));
                    oA[k] = make_float4(o0.x, o0.y, o1.x, o1.y);
                    o0 = unpack2(mul2(tB[2 * k], scB2));
                    o1 = unpack2(mul2(tB[2 * k + 1], scB2));
                    oB[k] = make_float4(o0.x, o0.y, o1.x, o1.y);
                }
            }
            __syncwarp();

            // ---- cooperative coalesced store: 4 batch-rows per STG pass ----
            for (int k = lane; k < 256; k += 32) {
                int m = k >> 3, j = k & 7;
                const float* src = wrows + m * K2_ROW;
                float4 vA = *(const float4*)(src + j * 4);
                float4 vB = *(const float4*)(src + 64 + j * 4);
                size_t rowA = (((size_t)(g * 64 + m) * 7 + line) * 3 + p) * 32;
                size_t rowB = (((size_t)(g * 64 + 32 + m) * 7 + line) * 3 + p) * 32;
                *(float4*)(out + rowA + j * 4) = vA;
                *(float4*)(out + rowB + j * 4) = vB;
            }
            __syncwarp();
        }
    }
}

// ============================================================================
extern "C" void kernel_launch(void* const* d_in, const int* in_sizes, int n_in,
                              void* d_out, int out_size)
{
    const float* z      = (const float*)d_in[0];
    const float* gen_W1 = (const float*)d_in[1];
    const float* gen_b1 = (const float*)d_in[2];
    const float* gen_g  = (const float*)d_in[3];
    const float* gen_be = (const float*)d_in[4];
    const float* gen_W2 = (const float*)d_in[5];
    const float* gen_b2 = (const float*)d_in[6];
    const float* cf_W1  = (const float*)d_in[7];
    const float* cf_b1  = (const float*)d_in[8];
    const float* cf_W2  = (const float*)d_in[9];
    const float* cf_b2  = (const float*)d_in[10];
    const float* g_W    = (const float*)d_in[11];
    const float* g_b    = (const float*)d_in[12];
    const float* c_W1   = (const float*)d_in[13];
    const float* c_b1   = (const float*)d_in[14];
    const float* c_g    = (const float*)d_in[15];
    const float* c_be   = (const float*)d_in[16];
    const float* c_W2   = (const float*)d_in[17];
    const float* c_b2   = (const float*)d_in[18];

    float* out      = (float*)d_out;                       // composed [B,7,3,32]
    float* out_conf = out + (size_t)B_TOTAL * 672;         // comp_conf [B,7,3]

    cudaFuncSetAttribute(colony_k1, cudaFuncAttributeMaxDynamicSharedMemorySize, K1_SMEM);
    cudaFuncSetAttribute(colony_k2, cudaFuncAttributeMaxDynamicSharedMemorySize, K2_SMEM);

    colony_k1<<<148, K1_THREADS, K1_SMEM>>>(z, gen_W1, gen_b1, gen_g, gen_be, gen_W2, gen_b2,
                                            cf_W1, cf_b1, cf_W2, cf_b2, g_W, g_b, out_conf);
    colony_kt<<<B_TOTAL / 32, 256>>>();
    colony_k2<<<K2_GRID, K2_THREADS, K2_SMEM>>>(c_W1, c_b1, c_g, c_be, c_W2, c_b2, out);
}

// round 12
// speedup vs baseline: 2.3551x; 1.0890x over previous
#include <cuda_runtime.h>
#include <math.h>

#define B_TOTAL 65536
#define NBLK (B_TOTAL / 32)
#define NL 7

typedef unsigned long long u64;

// ---- scratch (static device globals) ----
__device__ __align__(16) float g_traces_blk[(size_t)B_TOTAL * 224];   // [blk][c][d][32]
__device__ __align__(16) float g_gates_T[(size_t)NL * B_TOTAL];       // [line][b]
__device__ __align__(16) float g_z_blk[(size_t)B_TOTAL * 98];         // [blk][98][32]

__constant__ int FSRC[21] = {0,1,2, 0,3,4, 0,5,6, 1,3,5, 1,4,6, 2,3,6, 2,4,5};
__constant__ int FPAR[21] = {1,2,0, 3,4,0, 5,6,0, 3,5,1, 4,6,1, 3,6,2, 4,5,2};

__device__ __forceinline__ u64 pack2(float x, float y) {
    u64 r; asm("mov.b64 %0, {%1,%2};" : "=l"(r) : "f"(x), "f"(y)); return r;
}
__device__ __forceinline__ float2 unpack2(u64 v) {
    float2 r; asm("mov.b64 {%0,%1}, %2;" : "=f"(r.x), "=f"(r.y) : "l"(v)); return r;
}
__device__ __forceinline__ u64 dup2(float x) { return pack2(x, x); }
__device__ __forceinline__ u64 ffma2(u64 a, u64 b, u64 c) {
    u64 d; asm("fma.rn.f32x2 %0, %1, %2, %3;" : "=l"(d) : "l"(a), "l"(b), "l"(c)); return d;
}
__device__ __forceinline__ u64 add2(u64 a, u64 b) {
    u64 d; asm("add.rn.f32x2 %0, %1, %2;" : "=l"(d) : "l"(a), "l"(b)); return d;
}
__device__ __forceinline__ u64 mul2(u64 a, u64 b) {
    u64 d; asm("mul.rn.f32x2 %0, %1, %2;" : "=l"(d) : "l"(a), "l"(b)); return d;
}

__device__ __forceinline__ float fast_sigmoid(float x) {
    return __fdividef(1.0f, 1.0f + __expf(-x));
}

__device__ __forceinline__ float colony_act(int c, float x) {
    switch (c) {
        case 0: return fmaxf(x, 0.0f);
        case 1: { float e = __expf(2.0f * x); return 1.0f - __fdividef(2.0f, e + 1.0f); }
        case 2: return 0.5f * x * (1.0f + erff(x * 0.7071067811865476f));
        case 3: return x * fast_sigmoid(x);
        case 4: return fmaxf(x, 0.0f) + log1pf(__expf(-fabsf(x)));
        case 5: return fast_sigmoid(x);
        default: return fminf(fmaxf(x, -1.0f), 1.0f);
    }
}

// ============================================================================
// Kernel Z: transpose z [B][98] -> z_blk [blk][98][32]  (pure bandwidth)
// ============================================================================
__global__ void __launch_bounds__(256, 4)
colony_kz(const float* __restrict__ z)
{
    __shared__ float tile[32 * 99];
    const int blk = blockIdx.x;
    const float* src = z + (size_t)blk * 3136;
    for (int idx = threadIdx.x; idx < 3136; idx += 256) {
        int b = idx / 98, q = idx % 98;
        tile[b * 99 + q] = src[idx];
    }
    __syncthreads();
    float* dst = g_z_blk + (size_t)blk * 3136;
    for (int idx = threadIdx.x; idx < 3136; idx += 256) {
        int q = idx >> 5, bb = idx & 31;
        dst[idx] = tile[bb * 99 + q];
    }
}

// ============================================================================
// Kernel 1 (NEW): lane = batch. Warp = 32 batches = one block of g_traces_blk.
// Broadcast weight LDS.128; per-lane serial LN/l2norm (no shuffles); gates
// accumulated per-colony from trace registers; writes blocked layouts directly.
// ============================================================================
#define K1_WARPS 7
#define K1_THREADS (K1_WARPS * 32)
#define K1_ROW 100   // h [0,64) | conf [64,71) | pad ; 100 = 4*25 -> conflict-free float4
#define K1_WSZ (27344 + K1_WARPS * 32 * K1_ROW)
#define K1_SMEM (K1_WSZ * 4)

__global__ void __launch_bounds__(K1_THREADS, 1)
colony_k1(const float* __restrict__ gen_W1, const float* __restrict__ gen_b1,
          const float* __restrict__ gen_g,  const float* __restrict__ gen_be,
          const float* __restrict__ gen_W2, const float* __restrict__ gen_b2,
          const float* __restrict__ cf_W1,  const float* __restrict__ cf_b1,
          const float* __restrict__ cf_W2,  const float* __restrict__ cf_b2,
          const float* __restrict__ gw,     const float* __restrict__ gb,
          float* __restrict__ out_conf)
{
    extern __shared__ __align__(16) float sm[];
    float* sW1  = sm;            // 6272  [7][14][64]
    float* sb1  = sW1  + 6272;   // 448
    float* sg   = sb1  + 448;    // 448
    float* sbe  = sg   + 448;    // 448
    float* sW2  = sbe  + 448;    // 14336 [7][64][32]
    float* sb2  = sW2  + 14336;  // 224
    float* scW1 = sb2  + 224;    // 3136  [7][14][32]
    float* scb1 = scW1 + 3136;   // 224
    float* scW2 = scb1 + 224;    // 224
    float* scb2 = scW2 + 224;    // 8
    float* sgWT = scb2 + 8;      // 1568  transposed [7][224]
    float* sgb  = sgWT + 1568;   // 8
    float* rows = sgb  + 8;

    const int tid = threadIdx.x;
    for (int i = tid; i < 6272;  i += blockDim.x) sW1[i]  = gen_W1[i];
    for (int i = tid; i < 448;   i += blockDim.x) sb1[i]  = gen_b1[i];
    for (int i = tid; i < 448;   i += blockDim.x) sg[i]   = gen_g[i];
    for (int i = tid; i < 448;   i += blockDim.x) sbe[i]  = gen_be[i];
    for (int i = tid; i < 14336; i += blockDim.x) sW2[i]  = gen_W2[i];
    for (int i = tid; i < 224;   i += blockDim.x) sb2[i]  = gen_b2[i];
    for (int i = tid; i < 3136;  i += blockDim.x) scW1[i] = cf_W1[i];
    for (int i = tid; i < 224;   i += blockDim.x) scb1[i] = cf_b1[i];
    for (int i = tid; i < 224;   i += blockDim.x) scW2[i] = cf_W2[i];
    for (int i = tid; i < 7;     i += blockDim.x) scb2[i] = cf_b2[i];
    for (int i = tid; i < 1568;  i += blockDim.x) {
        int l = i / 224, d = i % 224;
        sgWT[i] = gw[d * 7 + l];
    }
    for (int i = tid; i < 7;     i += blockDim.x) sgb[i]  = gb[i];
    __syncthreads();

    const int wid  = tid >> 5;
    const int lane = tid & 31;
    float* myrow = rows + (wid * 32 + lane) * K1_ROW;

    const int gwarp = blockIdx.x * K1_WARPS + wid;
    const int nwarp = gridDim.x * K1_WARPS;

    for (int blk = gwarp; blk < NBLK; blk += nwarp) {
        const int b = blk * 32 + lane;
        u64 gacc[7];
#pragma unroll
        for (int l = 0; l < 7; l++) gacc[l] = 0ull;

        for (int c = 0; c < NL; c++) {
            // ---- x[14] coalesced from blocked z ----
            float x[14];
            const float* zb = g_z_blk + (size_t)blk * 3136 + c * 14 * 32 + lane;
#pragma unroll
            for (int q = 0; q < 14; q++) x[q] = zb[q * 32];

            // ---- stage 1: h = x @ W1 + b1, two 32-col chunks ----
            float s1 = 0.0f, s2 = 0.0f;
            for (int chunk = 0; chunk < 2; chunk++) {
                u64 h[16];
                {
                    const ulonglong2* bp = (const ulonglong2*)(sb1 + c * 64 + chunk * 32);
#pragma unroll
                    for (int k = 0; k < 8; k++) {
                        ulonglong2 bv = bp[k];
                        h[2 * k] = bv.x; h[2 * k + 1] = bv.y;
                    }
                }
                const float* Wb = sW1 + c * (14 * 64) + chunk * 32;
#pragma unroll
                for (int q = 0; q < 14; q++) {
                    u64 xd = dup2(x[q]);
                    const ulonglong2* wr = (const ulonglong2*)(Wb + q * 64);
#pragma unroll
                    for (int jj = 0; jj < 8; jj++) {
                        ulonglong2 w = wr[jj];
                        h[2 * jj]     = ffma2(xd, w.x, h[2 * jj]);
                        h[2 * jj + 1] = ffma2(xd, w.y, h[2 * jj + 1]);
                    }
                }
                // stats + park
                u64 sp = h[0], qp = mul2(h[0], h[0]);
#pragma unroll
                for (int k = 1; k < 16; k++) {
                    sp = add2(sp, h[k]);
                    qp = ffma2(h[k], h[k], qp);
                }
                float2 fs = unpack2(sp), fq = unpack2(qp);
                s1 += fs.x + fs.y;
                s2 += fq.x + fq.y;
                float4* hst = (float4*)(myrow + chunk * 32);
#pragma unroll
                for (int k = 0; k < 8; k++) {
                    float2 lo = unpack2(h[2 * k]);
                    float2 hi = unpack2(h[2 * k + 1]);
                    hst[k] = make_float4(lo.x, lo.y, hi.x, hi.y);
                }
            }
            const float m  = s1 * (1.0f / 64.0f);
            const float var = fmaxf(s2 * (1.0f / 64.0f) - m * m, 0.0f);
            const float iv  = rsqrtf(var + 1e-5f);

            // ---- stage 2: t = ACT(LN(h)) @ W2 + b2 (fused) ----
            u64 t[16];
            {
                const ulonglong2* bp = (const ulonglong2*)(sb2 + c * 32);
#pragma unroll
                for (int k = 0; k < 8; k++) {
                    ulonglong2 bv = bp[k];
                    t[2 * k] = bv.x; t[2 * k + 1] = bv.y;
                }
            }
            for (int r0 = 0; r0 < 16; r0++) {
                float4 hv = ((const float4*)myrow)[r0];
                float4 gv = *(const float4*)(sg + c * 64 + r0 * 4);
                float4 bv = *(const float4*)(sbe + c * 64 + r0 * 4);
#pragma unroll
                for (int r = 0; r < 4; r++) {
                    float hh = (r == 0) ? hv.x : (r == 1) ? hv.y : (r == 2) ? hv.z : hv.w;
                    float gg = (r == 0) ? gv.x : (r == 1) ? gv.y : (r == 2) ? gv.z : gv.w;
                    float bb = (r == 0) ? bv.x : (r == 1) ? bv.y : (r == 2) ? bv.z : bv.w;
                    float av = colony_act(c, fmaf((hh - m) * iv, gg, bb));
                    u64 ad = dup2(av);
                    const ulonglong2* wr = (const ulonglong2*)(sW2 + c * 2048 + (r0 * 4 + r) * 32);
#pragma unroll
                    for (int k = 0; k < 8; k++) {
                        ulonglong2 w = wr[k];
                        t[2 * k]     = ffma2(ad, w.x, t[2 * k]);
                        t[2 * k + 1] = ffma2(ad, w.y, t[2 * k + 1]);
                    }
                }
            }
            // ---- l2norm (per-lane) ----
            u64 nq = mul2(t[0], t[0]);
#pragma unroll
            for (int k = 1; k < 16; k++) nq = ffma2(t[k], t[k], nq);
            float2 nf = unpack2(nq);
            u64 nd = dup2(rsqrtf(fmaxf(nf.x + nf.y, 1e-24f)));
#pragma unroll
            for (int k = 0; k < 16; k++) t[k] = mul2(t[k], nd);

            // ---- store blocked traces (coalesced STG.32 per dim) ----
            {
                float* tb = g_traces_blk + (size_t)blk * 7168 + c * 1024 + lane;
#pragma unroll
                for (int k = 0; k < 16; k++) {
                    float2 f = unpack2(t[k]);
                    tb[(2 * k) * 32]     = f.x;
                    tb[(2 * k + 1) * 32] = f.y;
                }
            }
            // ---- accumulate gates from trace regs ----
#pragma unroll
            for (int l = 0; l < 7; l++) {
                const ulonglong2* gp = (const ulonglong2*)(sgWT + l * 224 + c * 32);
                u64 acc = gacc[l];
#pragma unroll
                for (int k = 0; k < 8; k++) {
                    ulonglong2 w = gp[k];
                    acc = ffma2(t[2 * k], w.x, acc);
                    acc = ffma2(t[2 * k + 1], w.y, acc);
                }
                gacc[l] = acc;
            }
            // ---- confidence head ----
            {
                u64 hc[16];
                const ulonglong2* bp = (const ulonglong2*)(scb1 + c * 32);
#pragma unroll
                for (int k = 0; k < 8; k++) {
                    ulonglong2 bv = bp[k];
                    hc[2 * k] = bv.x; hc[2 * k + 1] = bv.y;
                }
                const float* cw = scW1 + c * 448;
#pragma unroll
                for (int q = 0; q < 14; q++) {
                    u64 xd = dup2(x[q]);
                    const ulonglong2* wr = (const ulonglong2*)(cw + q * 32);
#pragma unroll
                    for (int k = 0; k < 8; k++) {
                        ulonglong2 w = wr[k];
                        hc[2 * k]     = ffma2(xd, w.x, hc[2 * k]);
                        hc[2 * k + 1] = ffma2(xd, w.y, hc[2 * k + 1]);
                    }
                }
                float dacc = 0.0f;
                const u64* w2p = (const u64*)(scW2 + c * 32);
#pragma unroll
                for (int k = 0; k < 16; k++) {
                    float2 hh = unpack2(hc[k]);
                    float2 ww = unpack2(w2p[k]);
                    dacc = fmaf(fmaxf(hh.x, 0.0f), ww.x, dacc);
                    dacc = fmaf(fmaxf(hh.y, 0.0f), ww.y, dacc);
                }
                myrow[64 + c] = fast_sigmoid(dacc + scb2[c]);
            }
        }

        // ---- gates final + stores ----
        float gate[7];
#pragma unroll
        for (int l = 0; l < 7; l++) {
            float2 f = unpack2(gacc[l]);
            gate[l] = fast_sigmoid(f.x + f.y + sgb[l]);
            g_gates_T[(size_t)l * B_TOTAL + b] = gate[l];
        }
        float cf[7];
#pragma unroll
        for (int i = 0; i < 7; i++) cf[i] = myrow[64 + i];
#pragma unroll
        for (int j = 0; j < 21; j++) {
            float gl = gate[j / 3];
            float v = (gl >= 0.3f) ? cf[FSRC[j]] * cf[FPAR[j]] * gl : 0.0f;
            out_conf[(size_t)b * 21 + j] = v;
        }
    }
}

// ============================================================================
// Kernel 2: unchanged from round 11 (proven).
// ============================================================================
#define K2_WARPS 10
#define K2_THREADS (K2_WARPS * 32)
#define K2_BLK_PER_LINE 21
#define K2_GRID (NL * K2_BLK_PER_LINE)
#define K2_ROW 132
#define K2_WSZ (6368 + K2_WARPS * 32 * K2_ROW)
#define K2_SMEM (K2_WSZ * 4)

__global__ void __launch_bounds__(K2_THREADS, 1)
colony_k2(const float* __restrict__ cW1, const float* __restrict__ cb1,
          const float* __restrict__ cg,  const float* __restrict__ cbe,
          const float* __restrict__ cW2, const float* __restrict__ cb2,
          float* __restrict__ out)
{
    extern __shared__ __align__(16) float sm[];
    float* sW1 = sm;
    float* sW2 = sW1 + 4096;
    float* sb1 = sW2 + 2048;
    float* sgl = sb1 + 64;
    float* sbe = sgl + 64;
    float* sb2 = sbe + 64;
    float* stile = sb2 + 32;

    const int line = blockIdx.x % NL;
    const int tid = threadIdx.x;
    {
        const float* w1 = cW1 + line * 4096;
        const float* w2 = cW2 + line * 2048;
        for (int i = tid; i < 4096; i += blockDim.x) sW1[i] = w1[i];
        for (int i = tid; i < 2048; i += blockDim.x) sW2[i] = w2[i];
        if (tid < 64) {
            sb1[tid] = cb1[line * 64 + tid];
            sgl[tid] = cg[line * 64 + tid];
            sbe[tid] = cbe[line * 64 + tid];
        }
        if (tid < 32) sb2[tid] = cb2[line * 32 + tid];
    }
    __syncthreads();

    const int wid  = tid >> 5;
    const int lane = tid & 31;
    float* myrow = stile + (wid * 32 + lane) * K2_ROW;
    float* wrows = stile + (wid * 32) * K2_ROW;

    const int col0 = FSRC[line * 3 + 0];
    const int col1 = FSRC[line * 3 + 1];
    const int col2 = FSRC[line * 3 + 2];

    const int lwarp = (blockIdx.x / NL) * K2_WARPS + wid;
    const int nlw   = K2_BLK_PER_LINE * K2_WARPS;
    const int ngroups = B_TOTAL / 64;

    for (int g = lwarp; g < ngroups; g += nlw) {
        const int blkA = 2 * g, blkB = 2 * g + 1;
        const int bA = g * 64 + lane;
        const int bB = bA + 32;

        const float gateA = g_gates_T[(size_t)line * B_TOTAL + bA];
        const float gateB = g_gates_T[(size_t)line * B_TOTAL + bB];
        const float sclA = (gateA >= 0.3f) ? gateA : 0.0f;
        const float sclB = (gateB >= 0.3f) ? gateB : 0.0f;

        for (int p = 0; p < 3; p++) {
            const int cS = (p == 0) ? col0 : (p == 1) ? col1 : col2;
            const int cP = (p == 0) ? col1 : (p == 1) ? col2 : col0;

            float s1A = 0.0f, s2A = 0.0f, s1B = 0.0f, s2B = 0.0f;
            for (int chunk = 0; chunk < 2; chunk++) {
                u64 hA[16], hB[16];
                {
                    const ulonglong2* bp = (const ulonglong2*)(sb1 + chunk * 32);
#pragma unroll
                    for (int k = 0; k < 8; k++) {
                        ulonglong2 bv = bp[k];
                        hA[2 * k] = bv.x; hA[2 * k + 1] = bv.y;
                        hB[2 * k] = bv.x; hB[2 * k + 1] = bv.y;
                    }
                }
                for (int half = 0; half < 2; half++) {
                    const int colony = half ? cP : cS;
                    const float* xA = g_traces_blk + (size_t)blkA * 7168 + colony * 1024 + lane;
                    const float* xB = g_traces_blk + (size_t)blkB * 7168 + colony * 1024 + lane;
                    const float* Wb = sW1 + half * 2048 + chunk * 32;
#pragma unroll 8
                    for (int i = 0; i < 32; i++) {
                        u64 aD = dup2(xA[i * 32]);
                        u64 bD = dup2(xB[i * 32]);
                        const ulonglong2* wr = (const ulonglong2*)(Wb + i * 64);
#pragma unroll
                        for (int jj = 0; jj < 8; jj++) {
                            ulonglong2 w = wr[jj];
                            hA[2 * jj]     = ffma2(aD, w.x, hA[2 * jj]);
                            hA[2 * jj + 1] = ffma2(aD, w.y, hA[2 * jj + 1]);
                            hB[2 * jj]     = ffma2(bD, w.x, hB[2 * jj]);
                            hB[2 * jj + 1] = ffma2(bD, w.y, hB[2 * jj + 1]);
                        }
                    }
                }
                {
                    u64 sAp = hA[0], qAp = mul2(hA[0], hA[0]);
                    u64 sBp = hB[0], qBp = mul2(hB[0], hB[0]);
#pragma unroll
                    for (int k = 1; k < 16; k++) {
                        sAp = add2(sAp, hA[k]); qAp = ffma2(hA[k], hA[k], qAp);
                        sBp = add2(sBp, hB[k]); qBp = ffma2(hB[k], hB[k], qBp);
                    }
                    float2 a1 = unpack2(sAp), a2 = unpack2(qAp);
                    float2 b1 = unpack2(sBp), b2 = unpack2(qBp);
                    s1A += a1.x + a1.y;  s2A += a2.x + a2.y;
                    s1B += b1.x + b1.y;  s2B += b2.x + b2.y;
                }
                {
                    float4* hstA = (float4*)(myrow + chunk * 32);
                    float4* hstB = (float4*)(myrow + 64 + chunk * 32);
#pragma unroll
                    for (int k = 0; k < 8; k++) {
                        float2 lo = unpack2(hA[2 * k]);
                        float2 hi = unpack2(hA[2 * k + 1]);
                        hstA[k] = make_float4(lo.x, lo.y, hi.x, hi.y);
                        lo = unpack2(hB[2 * k]);
                        hi = unpack2(hB[2 * k + 1]);
                        hstB[k] = make_float4(lo.x, lo.y, hi.x, hi.y);
                    }
                }
            }
            const float mA = s1A * (1.0f / 64.0f);
            const float mB = s1B * (1.0f / 64.0f);
            const float ivA = rsqrtf(fmaxf(s2A * (1.0f / 64.0f) - mA * mA, 0.0f) + 1e-5f);
            const float ivB = rsqrtf(fmaxf(s2B * (1.0f / 64.0f) - mB * mB, 0.0f) + 1e-5f);

            u64 tA[16], tB[16];
            {
                const ulonglong2* bp = (const ulonglong2*)sb2;
#pragma unroll
                for (int k = 0; k < 8; k++) {
                    ulonglong2 bv = bp[k];
                    tA[2 * k] = bv.x; tA[2 * k + 1] = bv.y;
                    tB[2 * k] = bv.x; tB[2 * k + 1] = bv.y;
                }
            }
#pragma unroll 4
            for (int r0 = 0; r0 < 16; r0++) {
                float4 hvA = ((const float4*)myrow)[r0];
                float4 hvB = ((const float4*)(myrow + 64))[r0];
                float4 gv = ((const float4*)sgl)[r0];
                float4 bv = ((const float4*)sbe)[r0];
#pragma unroll
                for (int r = 0; r < 4; r++) {
                    float hA1 = (r == 0) ? hvA.x : (r == 1) ? hvA.y : (r == 2) ? hvA.z : hvA.w;
                    float hB1 = (r == 0) ? hvB.x : (r == 1) ? hvB.y : (r == 2) ? hvB.z : hvB.w;
                    float gw1 = (r == 0) ? gv.x : (r == 1) ? gv.y : (r == 2) ? gv.z : gv.w;
                    float bw1 = (r == 0) ? bv.x : (r == 1) ? bv.y : (r == 2) ? bv.z : bv.w;
                    float aAv = fmaxf(fmaf((hA1 - mA) * ivA, gw1, bw1), 0.0f);
                    float aBv = fmaxf(fmaf((hB1 - mB) * ivB, gw1, bw1), 0.0f);
                    u64 aD = dup2(aAv);
                    u64 bD = dup2(aBv);
                    const ulonglong2* wr = (const ulonglong2*)(sW2 + (r0 * 4 + r) * 32);
#pragma unroll
                    for (int k = 0; k < 8; k++) {
                        ulonglong2 w = wr[k];
                        tA[2 * k]     = ffma2(aD, w.x, tA[2 * k]);
                        tA[2 * k + 1] = ffma2(aD, w.y, tA[2 * k + 1]);
                        tB[2 * k]     = ffma2(bD, w.x, tB[2 * k]);
                        tB[2 * k + 1] = ffma2(bD, w.y, tB[2 * k + 1]);
                    }
                }
            }
            {
                u64 nqA = mul2(tA[0], tA[0]);
                u64 nqB = mul2(tB[0], tB[0]);
#pragma unroll
                for (int k = 1; k < 16; k++) {
                    nqA = ffma2(tA[k], tA[k], nqA);
                    nqB = ffma2(tB[k], tB[k], nqB);
                }
                float2 fa = unpack2(nqA), fb = unpack2(nqB);
                u64 scA2 = dup2(sclA * rsqrtf(fmaxf(fa.x + fa.y, 1e-24f)));
                u64 scB2 = dup2(sclB * rsqrtf(fmaxf(fb.x + fb.y, 1e-24f)));
                float4* oA = (float4*)myrow;
                float4* oB = (float4*)(myrow + 64);
#pragma unroll
                for (int k = 0; k < 8; k++) {
                    float2 o0 = unpack2(mul2(tA[2 * k], scA2));
                    float2 o1 = unpack2(mul2(tA[2 * k + 1], scA2));
                    oA[k] = make_float4(o0.x, o0.y, o1.x, o1.y);
                    o0 = unpack2(mul2(tB[2 * k], scB2));
                    o1 = unpack2(mul2(tB[2 * k + 1], scB2));
                    oB[k] = make_float4(o0.x, o0.y, o1.x, o1.y);
                }
            }
            __syncwarp();

            for (int k = lane; k < 256; k += 32) {
                int m = k >> 3, j = k & 7;
                const float* src = wrows + m * K2_ROW;
                float4 vA = *(const float4*)(src + j * 4);
                float4 vB = *(const float4*)(src + 64 + j * 4);
                size_t rowA = (((size_t)(g * 64 + m) * 7 + line) * 3 + p) * 32;
                size_t rowB = (((size_t)(g * 64 + 32 + m) * 7 + line) * 3 + p) * 32;
                *(float4*)(out + rowA + j * 4) = vA;
                *(float4*)(out + rowB + j * 4) = vB;
            }
            __syncwarp();
        }
    }
}

// ============================================================================
extern "C" void kernel_launch(void* const* d_in, const int* in_sizes, int n_in,
                              void* d_out, int out_size)
{
    const float* z      = (const float*)d_in[0];
    const float* gen_W1 = (const float*)d_in[1];
    const float* gen_b1 = (const float*)d_in[2];
    const float* gen_g  = (const float*)d_in[3];
    const float* gen_be = (const float*)d_in[4];
    const float* gen_W2 = (const float*)d_in[5];
    const float* gen_b2 = (const float*)d_in[6];
    const float* cf_W1  = (const float*)d_in[7];
    const float* cf_b1  = (const float*)d_in[8];
    const float* cf_W2  = (const float*)d_in[9];
    const float* cf_b2  = (const float*)d_in[10];
    const float* g_W    = (const float*)d_in[11];
    const float* g_b    = (const float*)d_in[12];
    const float* c_W1   = (const float*)d_in[13];
    const float* c_b1   = (const float*)d_in[14];
    const float* c_g    = (const float*)d_in[15];
    const float* c_be   = (const float*)d_in[16];
    const float* c_W2   = (const float*)d_in[17];
    const float* c_b2   = (const float*)d_in[18];

    float* out      = (float*)d_out;                       // composed [B,7,3,32]
    float* out_conf = out + (size_t)B_TOTAL * 672;         // comp_conf [B,7,3]

    cudaFuncSetAttribute(colony_k1, cudaFuncAttributeMaxDynamicSharedMemorySize, K1_SMEM);
    cudaFuncSetAttribute(colony_k2, cudaFuncAttributeMaxDynamicSharedMemorySize, K2_SMEM);

    colony_kz<<<NBLK, 256>>>(z);
    colony_k1<<<148, K1_THREADS, K1_SMEM>>>(gen_W1, gen_b1, gen_g, gen_be, gen_W2, gen_b2,
                                            cf_W1, cf_b1, cf_W2, cf_b2, g_W, g_b, out_conf);
    colony_k2<<<K2_GRID, K2_THREADS, K2_SMEM>>>(c_W1, c_b1, c_g, c_be, c_W2, c_b2, out);
}